// round 10
// baseline (speedup 1.0000x reference)
#include <cuda_runtime.h>
#include <cuda_bf16.h>
#include <math.h>
#include <cstdint>

#define BATCH 1024
#define L 32
#define D 128
#define NNODE 50000
#define ROWS (BATCH * L)           // 32768
#define RD   (ROWS * D)            // 4194304
#define BD   (BATCH * D)           // 131072
#define ED   (NNODE * D)           // 6400000

// ---------------- float scratch ----------------
#define F_HG   0L                   // [ROWS, 640] = hin|hout|gh(384); later [ROWS,384] gh2
#define F_GI   (5L * RD)            // [ROWS, 384]
#define F_FW2  (8L * RD)
#define F_FIN  (9L * RD)
#define F_TOTAL (10L * RD)
__device__ float g_f[F_TOTAL];
__device__ float g_bio[640];        // concat(b_in, b_out, zeros[384])

// ---------------- bf16 split planes ----------------
#define BO_GAH  0L
#define BO_GAL  ((long)RD)
#define BO_AH   (2L * RD)
#define BO_AL   (4L * RD)
#define BO_ITH  (6L * RD)
#define BO_ITL  (7L * RD)
#define BO_FNH  (8L * RD)
#define BO_FNL  (9L * RD)
#define BO_IEH  (10L * RD)
#define BO_IEL  (11L * RD)
#define BO_HSH  (12L * RD)
#define BO_HSL  (12L * RD + BD)
#define BO_EBH  (12L * RD + 2L * BD)
#define BO_EBL  (12L * RD + 2L * BD + ED)
#define BO_WZ   (12L * RD + 2L * BD + 2L * ED)
#define OW_WIOU (BO_WZ)              // merged [640,128]
#define OW_WA   (OW_WIOU + 163840L)  // [384,256]
#define OW_WI   (OW_WA + 196608L)    // [384,128]
#define OW_WH   (OW_WI + 98304L)
#define OW_W2   (OW_WH + 98304L)     // [128,128]
#define B_TOTAL (OW_W2 + 32768L)
__device__ __nv_bfloat16 g_bf[B_TOTAL];

// ---------------- helpers ----------------
__device__ __forceinline__ uint32_t smem_u32(const void* p) {
    uint32_t a;
    asm("{ .reg .u64 t; cvta.to.shared.u64 t, %1; cvt.u32.u64 %0, t; }" : "=r"(a) : "l"(p));
    return a;
}
__device__ __forceinline__ void wsplit(float v, __nv_bfloat16* hp, __nv_bfloat16* lp, long i) {
    __nv_bfloat16 h = __float2bfloat16(v);
    hp[i] = h;
    lp[i] = __float2bfloat16(v - __bfloat162float(h));
}
__device__ __forceinline__ float sigf(float x) { return 1.0f / (1.0f + expf(-x)); }

__device__ __forceinline__ void mma_bf16(float* d, const uint32_t* a, const uint32_t* b) {
    asm volatile(
        "mma.sync.aligned.m16n8k16.row.col.f32.bf16.bf16.f32 "
        "{%0,%1,%2,%3}, {%4,%5,%6,%7}, {%8,%9}, {%0,%1,%2,%3};"
        : "+f"(d[0]), "+f"(d[1]), "+f"(d[2]), "+f"(d[3])
        : "r"(a[0]), "r"(a[1]), "r"(a[2]), "r"(a[3]), "r"(b[0]), "r"(b[1]));
}
__device__ __forceinline__ void ldsm4(uint32_t* r, uint32_t a) {
    asm volatile("ldmatrix.sync.aligned.m8n8.x4.shared.b16 {%0,%1,%2,%3}, [%4];"
        : "=r"(r[0]), "=r"(r[1]), "=r"(r[2]), "=r"(r[3]) : "r"(a));
}

// ================= split-bf16 tensor-core GEMM =================
// C[M,N] = (Ah+Al)[M,K] @ (Bh+Bl)[N,K]^T (+bias), fp32 accum.
// Block 128x64, 8 warps (4m x 2n), warp tile 32x32, K-chunk 32.
// 2-stage cp.async pipeline, one __syncthreads per chunk, 3 CTAs/SM.
#define BM 128
#define BN 64
#define BK 32
#define APLB (128 * 80)             // A plane bytes (10240)
#define BPLB (64 * 80)              // B plane bytes (5120)
#define STAGEB (2 * APLB + 2 * BPLB)  // 30720
#define GEMM_SMEM (2 * STAGEB)        // 61440

__global__ void __launch_bounds__(256, 3) gemm_mma(
    long ah, long al, long bh, long bl,
    const float* __restrict__ bias_ext, int bias_mode,
    float* __restrict__ C_ext, long c_off, int N, int K)
{
    extern __shared__ __align__(16) __nv_bfloat16 dsm[];
    const __nv_bfloat16* Ah = g_bf + ah;
    const __nv_bfloat16* Al = g_bf + al;
    const __nv_bfloat16* Bh = g_bf + bh;
    const __nv_bfloat16* Bl = g_bf + bl;
    float* C = C_ext ? C_ext : (g_f + c_off);
    const float* bias = (bias_mode == 1) ? bias_ext : (bias_mode == 2 ? g_bio : nullptr);

    const int tid = threadIdx.x;
    const int warp = tid >> 5, lane = tid & 31;
    const int wm = warp >> 1, wn = warp & 1;          // 4m x 2n
    const int g = lane >> 2, tig = lane & 3;

    const long bm = (long)blockIdx.x * BM;
    const int bn = blockIdx.y * BN;
    const int nsize = min(BN, N - bn);

    // A fill: row fr (0..127), 2x16B per plane; B fill: row br (0..63), 1x16B per plane
    const int fr = tid >> 1;
    const int fc = (tid & 1) * 16;
    const int br = tid >> 2;
    const int bq = (tid & 3) * 8;
    const long arow = bm + fr;
    const long brow = bn + (br < nsize ? br : 0);
    const int bok = (br < nsize) ? 16 : 0;
    const uint32_t smb = smem_u32(dsm);
    const uint32_t doffA = (uint32_t)(fr * 80 + fc * 2);
    const uint32_t doffB = (uint32_t)(br * 80 + bq * 2);

    const uint32_t laneA = (uint32_t)(((lane & 7) + (((lane >> 3) & 1) << 3)) * 80 + (lane >> 4) * 16);
    const uint32_t laneB = (uint32_t)(((lane & 7) + ((lane >> 4) << 3)) * 80 + ((lane >> 3) & 1) * 16);
    const uint32_t aBaseA = (uint32_t)(wm * 32 * 80) + laneA;
    const uint32_t aBaseB = (uint32_t)(wn * 32 * 80) + laneB;

    float acc[2][4][4];
#pragma unroll
    for (int i = 0; i < 2; i++)
#pragma unroll
        for (int j = 0; j < 4; j++)
#pragma unroll
            for (int v = 0; v < 4; v++) acc[i][j][v] = 0.f;

#define LOADCH(c_, st_) do {                                                           \
    const long k0_ = (long)(c_) * BK;                                                  \
    const uint32_t b_ = smb + (uint32_t)(st_) * STAGEB;                                \
    const __nv_bfloat16* pa_ = Ah + arow * K + k0_ + fc;                               \
    const __nv_bfloat16* qa_ = Al + arow * K + k0_ + fc;                               \
    const __nv_bfloat16* pb_ = Bh + brow * K + k0_ + bq;                               \
    const __nv_bfloat16* qb_ = Bl + brow * K + k0_ + bq;                               \
    asm volatile("cp.async.cg.shared.global [%0], [%1], 16;" :: "r"(b_ + doffA), "l"(pa_)); \
    asm volatile("cp.async.cg.shared.global [%0], [%1], 16;" :: "r"(b_ + doffA + 16), "l"(pa_ + 8)); \
    asm volatile("cp.async.cg.shared.global [%0], [%1], 16;" :: "r"(b_ + APLB + doffA), "l"(qa_)); \
    asm volatile("cp.async.cg.shared.global [%0], [%1], 16;" :: "r"(b_ + APLB + doffA + 16), "l"(qa_ + 8)); \
    asm volatile("cp.async.cg.shared.global [%0], [%1], 16, %2;" :: "r"(b_ + 2 * APLB + doffB), "l"(pb_), "r"(bok)); \
    asm volatile("cp.async.cg.shared.global [%0], [%1], 16, %2;" :: "r"(b_ + 2 * APLB + BPLB + doffB), "l"(qb_), "r"(bok)); \
    asm volatile("cp.async.commit_group;");                                            \
} while (0)

    const int nch = K / BK;
    LOADCH(0, 0);
    for (int c = 0; c < nch; c++) {
        const int st = c & 1;
        asm volatile("cp.async.wait_group 0;");
        __syncthreads();
        if (c + 1 < nch) LOADCH(c + 1, st ^ 1);

        const uint32_t stb = smb + (uint32_t)st * STAGEB;
        const uint32_t pAh = stb + aBaseA;
        const uint32_t pAl = stb + APLB + aBaseA;
        const uint32_t pBh = stb + 2 * APLB + aBaseB;
        const uint32_t pBl = stb + 2 * APLB + BPLB + aBaseB;

#pragma unroll
        for (int ks = 0; ks < 2; ks++) {
            const uint32_t ko = (uint32_t)(ks * 32);
            uint32_t ahf[2][4], alf[2][4], bhf[4][2], blf[4][2];
#pragma unroll
            for (int mf = 0; mf < 2; mf++) {
                ldsm4(ahf[mf], pAh + (uint32_t)(mf * 16 * 80) + ko);
                ldsm4(alf[mf], pAl + (uint32_t)(mf * 16 * 80) + ko);
            }
#pragma unroll
            for (int np = 0; np < 2; np++) {
                uint32_t bt[4];
                ldsm4(bt, pBh + (uint32_t)(np * 16 * 80) + ko);
                bhf[np * 2][0] = bt[0]; bhf[np * 2][1] = bt[1];
                bhf[np * 2 + 1][0] = bt[2]; bhf[np * 2 + 1][1] = bt[3];
                ldsm4(bt, pBl + (uint32_t)(np * 16 * 80) + ko);
                blf[np * 2][0] = bt[0]; blf[np * 2][1] = bt[1];
                blf[np * 2 + 1][0] = bt[2]; blf[np * 2 + 1][1] = bt[3];
            }
#pragma unroll
            for (int mf = 0; mf < 2; mf++)
#pragma unroll
                for (int nf = 0; nf < 4; nf++) {
                    mma_bf16(acc[mf][nf], ahf[mf], bhf[nf]);
                    mma_bf16(acc[mf][nf], ahf[mf], blf[nf]);
                    mma_bf16(acc[mf][nf], alf[mf], bhf[nf]);
                }
        }
    }

#pragma unroll
    for (int mf = 0; mf < 2; mf++) {
        const long row = bm + wm * 32 + mf * 16 + g;
#pragma unroll
        for (int nf = 0; nf < 4; nf++) {
            const int col = bn + wn * 32 + nf * 8 + tig * 2;
            if (col < N) {
                float bx = bias ? bias[col] : 0.f;
                float by = bias ? bias[col + 1] : 0.f;
                *(float2*)&C[row * N + col] =
                    make_float2(acc[mf][nf][0] + bx, acc[mf][nf][1] + by);
                *(float2*)&C[(row + 8) * N + col] =
                    make_float2(acc[mf][nf][2] + bx, acc[mf][nf][3] + by);
            }
        }
    }
#undef LOADCH
}

// ================= fused prep =================
#define PREP_TOTAL (32768L + 49152 + 640 + 98304 + 49152 + 49152 + 16384 + (long)ED + 2L * RD)
__global__ void __launch_bounds__(256) prep_all(
    const float* __restrict__ W_in, const float* __restrict__ b_in,
    const float* __restrict__ W_out, const float* __restrict__ b_out,
    const float* __restrict__ W_a, const float* __restrict__ U_h,
    const float* __restrict__ Wi, const float* __restrict__ Wh,
    const float* __restrict__ W2,
    const float* __restrict__ emb, const float* __restrict__ inter,
    const int* __restrict__ items)
{
    long i = (long)blockIdx.x * 256 + threadIdx.x;
    if (i < 32768) {
        int n = (int)(i >> 7), k = (int)(i & 127);
        float v = (n < 128) ? W_in[k * 128 + n] : W_out[k * 128 + (n - 128)];
        wsplit(v, g_bf + OW_WIOU, g_bf + OW_WIOU + 81920, i);
        return;
    }
    i -= 32768;
    if (i < 49152) {
        int n = (int)(i >> 7), k = (int)(i & 127);
        wsplit(U_h[(long)k * 384 + n], g_bf + OW_WIOU + 32768, g_bf + OW_WIOU + 81920 + 32768, i);
        return;
    }
    i -= 49152;
    if (i < 640) {
        g_bio[i] = (i < 128) ? b_in[i] : (i < 256 ? b_out[i - 128] : 0.f);
        return;
    }
    i -= 640;
    if (i < 98304) {
        int n = (int)(i >> 8), k = (int)(i & 255);
        wsplit(W_a[(long)k * 384 + n], g_bf + OW_WA, g_bf + OW_WA + 98304, i);
        return;
    }
    i -= 98304;
    if (i < 49152) {
        int n = (int)(i >> 7), k = (int)(i & 127);
        wsplit(Wi[(long)k * 384 + n], g_bf + OW_WI, g_bf + OW_WI + 49152, i);
        return;
    }
    i -= 49152;
    if (i < 49152) {
        int n = (int)(i >> 7), k = (int)(i & 127);
        wsplit(Wh[(long)k * 384 + n], g_bf + OW_WH, g_bf + OW_WH + 49152, i);
        return;
    }
    i -= 49152;
    if (i < 16384) {
        int n = (int)(i >> 7), k = (int)(i & 127);
        wsplit(W2[(long)k * 128 + n], g_bf + OW_W2, g_bf + OW_W2 + 16384, i);
        return;
    }
    i -= 16384;
    if (i < (long)ED) {
        wsplit(emb[i], g_bf + BO_EBH, g_bf + BO_EBH + (long)ED, i);
        return;
    }
    i -= (long)ED;
    if (i < (long)RD) {
        wsplit(inter[i], g_bf + BO_IEH, g_bf + BO_IEH + (long)RD, i);
        return;
    }
    i -= (long)RD;
    if (i < (long)RD) {
        int row = (int)(i >> 7), d = (int)(i & 127);
        wsplit(emb[(long)items[row] * D + d], g_bf + BO_GAH, g_bf + BO_GAL, i);
    }
}

// ================= adjacency =================
__global__ void __launch_bounds__(128) adj_kernel(const float* __restrict__ Ain, const float* __restrict__ Aout) {
    const float* hg = g_f + F_HG;
    const int b = blockIdx.x, d = threadIdx.x;
    __shared__ float sAi[L * L], sAo[L * L], shi[L * D], sho[L * D];
    const float* Aib = Ain + (long)b * L * L;
    const float* Aob = Aout + (long)b * L * L;
    for (int i = d; i < L * L; i += 128) { sAi[i] = Aib[i]; sAo[i] = Aob[i]; }
    for (int i = d; i < L * D; i += 128) {
        int m = i >> 7, dd = i & 127;
        long r = ((long)b * L + m) * 640;
        shi[i] = hg[r + dd];
        sho[i] = hg[r + 128 + dd];
    }
    __syncthreads();
    for (int l = 0; l < L; l++) {
        float si = 0.f, so = 0.f;
#pragma unroll 8
        for (int m = 0; m < L; m++) {
            si += sAi[l * L + m] * shi[m * D + d];
            so += sAo[l * L + m] * sho[m * D + d];
        }
        long o = ((long)b * L + l) * 256;
        wsplit(si, g_bf + BO_AH, g_bf + BO_AL, o + d);
        wsplit(so, g_bf + BO_AH, g_bf + BO_AL, o + 128 + d);
    }
}

// ================= GRU kernels =================
__global__ void __launch_bounds__(256) gru1_kernel(const int* __restrict__ items, const float* __restrict__ emb) {
    long i = (long)blockIdx.x * 256 + threadIdx.x;
    if (i >= (long)RD) return;
    int row = (int)(i >> 7), d = (int)(i & 127);
    const float* gi = g_f + F_GI + (long)row * 384;
    const float* gh = g_f + F_HG + (long)row * 640 + 256;
    float r = sigf(gi[d] + gh[d]);
    float z = sigf(gi[128 + d] + gh[128 + d]);
    float n = tanhf(gi[256 + d] + r * gh[256 + d]);
    float hp = emb[(long)items[row] * D + d];
    wsplit((1.f - z) * n + z * hp, g_bf + BO_ITH, g_bf + BO_ITL, i);
}

__global__ void __launch_bounds__(256) gru2_kernel(const float* __restrict__ inter) {
    long i = (long)blockIdx.x * 256 + threadIdx.x;
    if (i >= (long)RD) return;
    int row = (int)(i >> 7), d = (int)(i & 127);
    const float* gi = g_f + F_GI + (long)row * 384;
    const float* gh = g_f + F_HG + (long)row * 384;
    float r = sigf(gi[d] + gh[d]);
    float z = sigf(gi[128 + d] + gh[128 + d]);
    float n = tanhf(gi[256 + d] + r * gh[256 + d]);
    float v = (1.f - z) * n + z * inter[i];
    g_f[F_FIN + i] = v;
    wsplit(v, g_bf + BO_FNH, g_bf + BO_FNL, i);
}

// ================= attention readout =================
__global__ void __launch_bounds__(128) readout_kernel(
    const int* __restrict__ seq_len,
    const float* __restrict__ W1, const float* __restrict__ b1,
    const float* __restrict__ wq, const float* __restrict__ bq,
    const float* __restrict__ W3, const float* __restrict__ b3)
{
    const float* fin = g_f + F_FIN;
    const float* fW2 = g_f + F_FW2;
    const int b = blockIdx.x, d = threadIdx.x;
    __shared__ float svn[D], sg_sh[D], gmat[L * D], alpha[L];

    const int sl = seq_len[b];
    const float* finb = fin + (long)b * L * D;
    svn[d] = finb[(long)(sl - 1) * D + d];
    __syncthreads();

    float q = b1[d];
    for (int k = 0; k < D; k++) q += svn[k] * W1[k * D + d];

    const float* fW2b = fW2 + (long)b * L * D;
    for (int l = 0; l < L; l++)
        gmat[l * D + d] = sigf(q + fW2b[l * D + d]);
    __syncthreads();

    int w = d >> 5, lane = d & 31;
    for (int l = w; l < L; l += 4) {
        float p = 0.f;
        for (int kk = lane; kk < D; kk += 32) p += gmat[l * D + kk] * wq[kk];
#pragma unroll
        for (int off = 16; off; off >>= 1) p += __shfl_xor_sync(0xFFFFFFFFu, p, off);
        if (lane == 0) alpha[l] = p + bq[0];
    }
    __syncthreads();

    float sg = 0.f;
    for (int l = 0; l < sl; l++) sg += alpha[l] * finb[(long)l * D + d];
    sg_sh[d] = sg;
    __syncthreads();

    float o = b3[d];
    for (int k = 0; k < D; k++) {
        o += svn[k]   * W3[k * D + d];
        o += sg_sh[k] * W3[(D + k) * D + d];
    }
    wsplit(o, g_bf + BO_HSH, g_bf + BO_HSL, (long)b * D + d);
}

// ================= launcher =================
extern "C" void kernel_launch(void* const* d_in, const int* in_sizes, int n_in,
                              void* d_out, int out_size)
{
    const int*   items  = (const int*)d_in[0];
    const float* A_in   = (const float*)d_in[1];
    const float* A_out  = (const float*)d_in[2];
    const float* inter  = (const float*)d_in[3];
    const int*   seqlen = (const int*)d_in[4];
    const float* emb    = (const float*)d_in[5];
    const float* W_in   = (const float*)d_in[6];
    const float* b_in   = (const float*)d_in[7];
    const float* W_out  = (const float*)d_in[8];
    const float* b_out  = (const float*)d_in[9];
    const float* W_a    = (const float*)d_in[10];
    const float* U_h    = (const float*)d_in[11];
    const float* b_gru  = (const float*)d_in[12];
    const float* Wi     = (const float*)d_in[13];
    const float* bi     = (const float*)d_in[14];
    const float* Wh     = (const float*)d_in[15];
    const float* bh     = (const float*)d_in[16];
    const float* W1     = (const float*)d_in[17];
    const float* b1     = (const float*)d_in[18];
    const float* W2     = (const float*)d_in[19];
    const float* b2     = (const float*)d_in[20];
    const float* wq     = (const float*)d_in[21];
    const float* bq     = (const float*)d_in[22];
    const float* W3     = (const float*)d_in[23];
    const float* b3     = (const float*)d_in[24];
    float* scores = (float*)d_out;

    cudaFuncSetAttribute(gemm_mma, cudaFuncAttributeMaxDynamicSharedMemorySize, GEMM_SMEM);

    const int MT = ROWS / 128;   // 256 M-tiles

    prep_all<<<(int)((PREP_TOTAL + 255) / 256), 256>>>(W_in, b_in, W_out, b_out, W_a, U_h,
                                                       Wi, Wh, W2, emb, inter, items);
    // [hio | gh] = gathered @ [W_in|W_out|U_h] + [bio|0]   (N=640, K=128)
    gemm_mma<<<dim3(MT, 640 / BN), 256, GEMM_SMEM>>>(BO_GAH, BO_GAL, OW_WIOU, OW_WIOU + 81920,
                                                     nullptr, 2, nullptr, F_HG, 640, 128);
    adj_kernel<<<BATCH, 128>>>(A_in, A_out);
    gemm_mma<<<dim3(MT, 384 / BN), 256, GEMM_SMEM>>>(BO_AH, BO_AL, OW_WA, OW_WA + 98304,
                                                     b_gru, 1, nullptr, F_GI, 384, 256);
    gru1_kernel<<<(RD + 255) / 256, 256>>>(items, emb);
    gemm_mma<<<dim3(MT, 384 / BN), 256, GEMM_SMEM>>>(BO_ITH, BO_ITL, OW_WI, OW_WI + 49152,
                                                     bi, 1, nullptr, F_GI, 384, 128);
    gemm_mma<<<dim3(MT, 384 / BN), 256, GEMM_SMEM>>>(BO_IEH, BO_IEL, OW_WH, OW_WH + 49152,
                                                     bh, 1, nullptr, F_HG, 384, 128);
    gru2_kernel<<<(RD + 255) / 256, 256>>>(inter);
    gemm_mma<<<dim3(MT, 128 / BN), 256, GEMM_SMEM>>>(BO_FNH, BO_FNL, OW_W2, OW_W2 + 16384,
                                                     b2, 1, nullptr, F_FW2, 128, 128);
    readout_kernel<<<BATCH, 128>>>(seqlen, W1, b1, wq, bq, W3, b3);
    gemm_mma<<<dim3(BATCH / 128, (NNODE + BN - 1) / BN), 256, GEMM_SMEM>>>(
        BO_HSH, BO_HSL, BO_EBH, BO_EBL, nullptr, 0, scores, 0, NNODE, 128);
}

// round 11
// speedup vs baseline: 1.1080x; 1.1080x over previous
#include <cuda_runtime.h>
#include <cuda_bf16.h>
#include <cuda_fp16.h>
#include <math.h>
#include <cstdint>

#define BATCH 1024
#define L 32
#define D 128
#define NNODE 50000
#define ROWS (BATCH * L)           // 32768
#define RD   (ROWS * D)            // 4194304
#define BD   (BATCH * D)           // 131072
#define ED   (NNODE * D)           // 6400000

// ---------------- float scratch ----------------
#define F_HG   0L                   // [ROWS, 640] = hin|hout|gh(384); later [ROWS,384] gh2
#define F_GI   (5L * RD)            // [ROWS, 384]
#define F_FW2  (8L * RD)
#define F_FIN  (9L * RD)
#define F_TOTAL (10L * RD)
__device__ float g_f[F_TOTAL];
__device__ float g_bio[640];        // concat(b_in, b_out, zeros[384])

// ---------------- 16-bit planes (bf16 split pairs; fp16 singles for scores path) --
#define BO_GAH  0L
#define BO_GAL  ((long)RD)
#define BO_AH   (2L * RD)
#define BO_AL   (4L * RD)
#define BO_ITH  (6L * RD)
#define BO_ITL  (7L * RD)
#define BO_FNH  (8L * RD)
#define BO_FNL  (9L * RD)
#define BO_IEH  (10L * RD)
#define BO_IEL  (11L * RD)
#define BO_HSF  (12L * RD)                  // hs fp16 [1024,128]
#define BO_EBF  (12L * RD + BD)             // emb fp16 [50000,128]
#define BO_WZ   (12L * RD + BD + (long)ED)
#define OW_WIOU (BO_WZ)              // merged [640,128]
#define OW_WA   (OW_WIOU + 163840L)  // [384,256]
#define OW_WI   (OW_WA + 196608L)    // [384,128]
#define OW_WH   (OW_WI + 98304L)
#define OW_W2   (OW_WH + 98304L)     // [128,128]
#define B_TOTAL (OW_W2 + 32768L)
__device__ __nv_bfloat16 g_bf[B_TOTAL];

// ---------------- helpers ----------------
__device__ __forceinline__ uint32_t smem_u32(const void* p) {
    uint32_t a;
    asm("{ .reg .u64 t; cvta.to.shared.u64 t, %1; cvt.u32.u64 %0, t; }" : "=r"(a) : "l"(p));
    return a;
}
__device__ __forceinline__ void wsplit(float v, __nv_bfloat16* hp, __nv_bfloat16* lp, long i) {
    __nv_bfloat16 h = __float2bfloat16(v);
    hp[i] = h;
    lp[i] = __float2bfloat16(v - __bfloat162float(h));
}
__device__ __forceinline__ float sigf(float x) { return 1.0f / (1.0f + expf(-x)); }

__device__ __forceinline__ void mma_bf16(float* d, const uint32_t* a, const uint32_t* b) {
    asm volatile(
        "mma.sync.aligned.m16n8k16.row.col.f32.bf16.bf16.f32 "
        "{%0,%1,%2,%3}, {%4,%5,%6,%7}, {%8,%9}, {%0,%1,%2,%3};"
        : "+f"(d[0]), "+f"(d[1]), "+f"(d[2]), "+f"(d[3])
        : "r"(a[0]), "r"(a[1]), "r"(a[2]), "r"(a[3]), "r"(b[0]), "r"(b[1]));
}
__device__ __forceinline__ void mma_f16(float* d, const uint32_t* a, const uint32_t* b) {
    asm volatile(
        "mma.sync.aligned.m16n8k16.row.col.f32.f16.f16.f32 "
        "{%0,%1,%2,%3}, {%4,%5,%6,%7}, {%8,%9}, {%0,%1,%2,%3};"
        : "+f"(d[0]), "+f"(d[1]), "+f"(d[2]), "+f"(d[3])
        : "r"(a[0]), "r"(a[1]), "r"(a[2]), "r"(a[3]), "r"(b[0]), "r"(b[1]));
}
__device__ __forceinline__ void ldsm4(uint32_t* r, uint32_t a) {
    asm volatile("ldmatrix.sync.aligned.m8n8.x4.shared.b16 {%0,%1,%2,%3}, [%4];"
        : "=r"(r[0]), "=r"(r[1]), "=r"(r[2]), "=r"(r[3]) : "r"(a));
}

// ================= split-bf16 tensor-core GEMM (R9 proven-best config) ===========
// Block 128x128, 8 warps (2m x 4n), warp tile 64x32, K-chunk 32, 2 CTAs/SM.
#define BM 128
#define BN 128
#define BK 32
#define PLANE (128 * 40)
#define PLANEB (PLANE * 2)
#define STAGEB (4 * PLANEB)
#define GEMM_SMEM (2 * STAGEB)      // 81920

__global__ void __launch_bounds__(256, 2) gemm_mma(
    long ah, long al, long bh, long bl,
    const float* __restrict__ bias_ext, int bias_mode,
    float* __restrict__ C_ext, long c_off, int N, int K)
{
    extern __shared__ __align__(16) __nv_bfloat16 dsm[];
    const __nv_bfloat16* Ah = g_bf + ah;
    const __nv_bfloat16* Al = g_bf + al;
    const __nv_bfloat16* Bh = g_bf + bh;
    const __nv_bfloat16* Bl = g_bf + bl;
    float* C = C_ext ? C_ext : (g_f + c_off);
    const float* bias = (bias_mode == 1) ? bias_ext : (bias_mode == 2 ? g_bio : nullptr);

    const int tid = threadIdx.x;
    const int warp = tid >> 5, lane = tid & 31;
    const int wm = warp & 1, wn = warp >> 1;
    const int g = lane >> 2, tig = lane & 3;

    const long bm = (long)blockIdx.x * BM;
    const int bn = blockIdx.y * BN;
    const int nsize = min(BN, N - bn);

    const int fr = tid >> 1;
    const int fc = (tid & 1) * 16;
    const long arow = bm + fr;
    const long brow = bn + (fr < nsize ? fr : 0);
    const int bok = (fr < nsize) ? 16 : 0;
    const uint32_t smb = smem_u32(dsm);
    const uint32_t doff = (uint32_t)(fr * 80 + fc * 2);

    const uint32_t laneA = (uint32_t)(((lane & 7) + (((lane >> 3) & 1) << 3)) * 80 + (lane >> 4) * 16);
    const uint32_t laneB = (uint32_t)(((lane & 7) + ((lane >> 4) << 3)) * 80 + ((lane >> 3) & 1) * 16);
    const uint32_t aBaseA = (uint32_t)(wm * 64 * 80) + laneA;
    const uint32_t aBaseB = (uint32_t)(wn * 32 * 80) + laneB;

    float acc[4][4][4];
#pragma unroll
    for (int i = 0; i < 4; i++)
#pragma unroll
        for (int j = 0; j < 4; j++)
#pragma unroll
            for (int v = 0; v < 4; v++) acc[i][j][v] = 0.f;

#define LOADCH(c_, st_) do {                                                           \
    const long k0_ = (long)(c_) * BK;                                                  \
    const uint32_t b_ = smb + (uint32_t)(st_) * STAGEB;                                \
    const __nv_bfloat16* pa_ = Ah + arow * K + k0_ + fc;                               \
    const __nv_bfloat16* qa_ = Al + arow * K + k0_ + fc;                               \
    const __nv_bfloat16* pb_ = Bh + brow * K + k0_ + fc;                               \
    const __nv_bfloat16* qb_ = Bl + brow * K + k0_ + fc;                               \
    asm volatile("cp.async.cg.shared.global [%0], [%1], 16;" :: "r"(b_ + doff), "l"(pa_)); \
    asm volatile("cp.async.cg.shared.global [%0], [%1], 16;" :: "r"(b_ + doff + 16), "l"(pa_ + 8)); \
    asm volatile("cp.async.cg.shared.global [%0], [%1], 16;" :: "r"(b_ + PLANEB + doff), "l"(qa_)); \
    asm volatile("cp.async.cg.shared.global [%0], [%1], 16;" :: "r"(b_ + PLANEB + doff + 16), "l"(qa_ + 8)); \
    asm volatile("cp.async.cg.shared.global [%0], [%1], 16, %2;" :: "r"(b_ + 2 * PLANEB + doff), "l"(pb_), "r"(bok)); \
    asm volatile("cp.async.cg.shared.global [%0], [%1], 16, %2;" :: "r"(b_ + 2 * PLANEB + doff + 16), "l"(pb_ + 8), "r"(bok)); \
    asm volatile("cp.async.cg.shared.global [%0], [%1], 16, %2;" :: "r"(b_ + 3 * PLANEB + doff), "l"(qb_), "r"(bok)); \
    asm volatile("cp.async.cg.shared.global [%0], [%1], 16, %2;" :: "r"(b_ + 3 * PLANEB + doff + 16), "l"(qb_ + 8), "r"(bok)); \
    asm volatile("cp.async.commit_group;");                                            \
} while (0)

    const int nch = K / BK;
    LOADCH(0, 0);
    for (int c = 0; c < nch; c++) {
        const int st = c & 1;
        asm volatile("cp.async.wait_group 0;");
        __syncthreads();
        if (c + 1 < nch) LOADCH(c + 1, st ^ 1);

        const uint32_t stb = smb + (uint32_t)st * STAGEB;
        const uint32_t pAh = stb + aBaseA;
        const uint32_t pAl = stb + PLANEB + aBaseA;
        const uint32_t pBh = stb + 2 * PLANEB + aBaseB;
        const uint32_t pBl = stb + 3 * PLANEB + aBaseB;

#pragma unroll
        for (int ks = 0; ks < 2; ks++) {
            const uint32_t ko = (uint32_t)(ks * 32);
            uint32_t ahf[4][4], alf[4][4], bhf[4][2], blf[4][2];
#pragma unroll
            for (int mf = 0; mf < 4; mf++) {
                ldsm4(ahf[mf], pAh + (uint32_t)(mf * 16 * 80) + ko);
                ldsm4(alf[mf], pAl + (uint32_t)(mf * 16 * 80) + ko);
            }
#pragma unroll
            for (int np = 0; np < 2; np++) {
                uint32_t bt[4];
                ldsm4(bt, pBh + (uint32_t)(np * 16 * 80) + ko);
                bhf[np * 2][0] = bt[0]; bhf[np * 2][1] = bt[1];
                bhf[np * 2 + 1][0] = bt[2]; bhf[np * 2 + 1][1] = bt[3];
                ldsm4(bt, pBl + (uint32_t)(np * 16 * 80) + ko);
                blf[np * 2][0] = bt[0]; blf[np * 2][1] = bt[1];
                blf[np * 2 + 1][0] = bt[2]; blf[np * 2 + 1][1] = bt[3];
            }
#pragma unroll
            for (int mf = 0; mf < 4; mf++)
#pragma unroll
                for (int nf = 0; nf < 4; nf++) {
                    mma_bf16(acc[mf][nf], ahf[mf], bhf[nf]);
                    mma_bf16(acc[mf][nf], ahf[mf], blf[nf]);
                    mma_bf16(acc[mf][nf], alf[mf], bhf[nf]);
                }
        }
    }

#pragma unroll
    for (int mf = 0; mf < 4; mf++) {
        const long row = bm + wm * 64 + mf * 16 + g;
#pragma unroll
        for (int nf = 0; nf < 4; nf++) {
            const int col = bn + wn * 32 + nf * 8 + tig * 2;
            if (col < N) {
                float bx = bias ? bias[col] : 0.f;
                float by = bias ? bias[col + 1] : 0.f;
                *(float2*)&C[row * N + col] =
                    make_float2(acc[mf][nf][0] + bx, acc[mf][nf][1] + by);
                *(float2*)&C[(row + 8) * N + col] =
                    make_float2(acc[mf][nf][2] + bx, acc[mf][nf][3] + by);
            }
        }
    }
#undef LOADCH
}

// ================= single-pass fp16 GEMM (scores only) =================
// C[M,N] = A[M,K] @ B[N,K]^T, fp16 inputs, fp32 accum.
// Block 128x64, 8 warps (4m x 2n), warp tile 32x32, K-chunk 32, 3 CTAs/SM.
#define F_APLB (128 * 80)
#define F_BPLB (64 * 80)
#define F_STAGEB (F_APLB + F_BPLB)    // 15360
#define F16_SMEM (2 * F_STAGEB)       // 30720

__global__ void __launch_bounds__(256, 3) gemm_f16(
    long a_off, long b_off, float* __restrict__ C, int N, int K)
{
    extern __shared__ __align__(16) char dsm16[];
    const __half* A = reinterpret_cast<const __half*>(g_bf + a_off);
    const __half* B = reinterpret_cast<const __half*>(g_bf + b_off);

    const int tid = threadIdx.x;
    const int warp = tid >> 5, lane = tid & 31;
    const int wm = warp >> 1, wn = warp & 1;          // 4m x 2n
    const int g = lane >> 2, tig = lane & 3;

    const long bm = (long)blockIdx.x * 128;
    const int bn = blockIdx.y * 64;
    const int nsize = min(64, N - bn);

    const int fr = tid >> 1;
    const int fc = (tid & 1) * 16;
    const int br = tid >> 2;
    const int bq = (tid & 3) * 8;
    const long arow = bm + fr;
    const long brow = bn + (br < nsize ? br : 0);
    const int bok = (br < nsize) ? 16 : 0;
    const uint32_t smb = smem_u32(dsm16);
    const uint32_t doffA = (uint32_t)(fr * 80 + fc * 2);
    const uint32_t doffB = (uint32_t)(br * 80 + bq * 2);

    const uint32_t laneA = (uint32_t)(((lane & 7) + (((lane >> 3) & 1) << 3)) * 80 + (lane >> 4) * 16);
    const uint32_t laneB = (uint32_t)(((lane & 7) + ((lane >> 4) << 3)) * 80 + ((lane >> 3) & 1) * 16);
    const uint32_t aBaseA = (uint32_t)(wm * 32 * 80) + laneA;
    const uint32_t aBaseB = (uint32_t)(wn * 32 * 80) + laneB;

    float acc[2][4][4];
#pragma unroll
    for (int i = 0; i < 2; i++)
#pragma unroll
        for (int j = 0; j < 4; j++)
#pragma unroll
            for (int v = 0; v < 4; v++) acc[i][j][v] = 0.f;

#define LOADF(c_, st_) do {                                                            \
    const long k0_ = (long)(c_) * 32;                                                  \
    const uint32_t b_ = smb + (uint32_t)(st_) * F_STAGEB;                              \
    const __half* pa_ = A + arow * K + k0_ + fc;                                       \
    const __half* pb_ = B + brow * K + k0_ + bq;                                       \
    asm volatile("cp.async.cg.shared.global [%0], [%1], 16;" :: "r"(b_ + doffA), "l"(pa_)); \
    asm volatile("cp.async.cg.shared.global [%0], [%1], 16;" :: "r"(b_ + doffA + 16), "l"(pa_ + 8)); \
    asm volatile("cp.async.cg.shared.global [%0], [%1], 16, %2;" :: "r"(b_ + F_APLB + doffB), "l"(pb_), "r"(bok)); \
    asm volatile("cp.async.commit_group;");                                            \
} while (0)

    const int nch = K / 32;
    LOADF(0, 0);
    for (int c = 0; c < nch; c++) {
        const int st = c & 1;
        asm volatile("cp.async.wait_group 0;");
        __syncthreads();
        if (c + 1 < nch) LOADF(c + 1, st ^ 1);

        const uint32_t stb = smb + (uint32_t)st * F_STAGEB;
        const uint32_t pA = stb + aBaseA;
        const uint32_t pB = stb + F_APLB + aBaseB;

#pragma unroll
        for (int ks = 0; ks < 2; ks++) {
            const uint32_t ko = (uint32_t)(ks * 32);
            uint32_t af[2][4], bf[4][2];
#pragma unroll
            for (int mf = 0; mf < 2; mf++)
                ldsm4(af[mf], pA + (uint32_t)(mf * 16 * 80) + ko);
#pragma unroll
            for (int np = 0; np < 2; np++) {
                uint32_t bt[4];
                ldsm4(bt, pB + (uint32_t)(np * 16 * 80) + ko);
                bf[np * 2][0] = bt[0]; bf[np * 2][1] = bt[1];
                bf[np * 2 + 1][0] = bt[2]; bf[np * 2 + 1][1] = bt[3];
            }
#pragma unroll
            for (int mf = 0; mf < 2; mf++)
#pragma unroll
                for (int nf = 0; nf < 4; nf++)
                    mma_f16(acc[mf][nf], af[mf], bf[nf]);
        }
    }

#pragma unroll
    for (int mf = 0; mf < 2; mf++) {
        const long row = bm + wm * 32 + mf * 16 + g;
#pragma unroll
        for (int nf = 0; nf < 4; nf++) {
            const int col = bn + wn * 32 + nf * 8 + tig * 2;
            if (col < N) {
                *(float2*)&C[row * N + col] = make_float2(acc[mf][nf][0], acc[mf][nf][1]);
                *(float2*)&C[(row + 8) * N + col] = make_float2(acc[mf][nf][2], acc[mf][nf][3]);
            }
        }
    }
#undef LOADF
}

// ================= fused prep =================
#define PREP_TOTAL (32768L + 49152 + 640 + 98304 + 49152 + 49152 + 16384 + (long)ED + 2L * RD)
__global__ void __launch_bounds__(256) prep_all(
    const float* __restrict__ W_in, const float* __restrict__ b_in,
    const float* __restrict__ W_out, const float* __restrict__ b_out,
    const float* __restrict__ W_a, const float* __restrict__ U_h,
    const float* __restrict__ Wi, const float* __restrict__ Wh,
    const float* __restrict__ W2,
    const float* __restrict__ emb, const float* __restrict__ inter,
    const int* __restrict__ items)
{
    long i = (long)blockIdx.x * 256 + threadIdx.x;
    if (i < 32768) {
        int n = (int)(i >> 7), k = (int)(i & 127);
        float v = (n < 128) ? W_in[k * 128 + n] : W_out[k * 128 + (n - 128)];
        wsplit(v, g_bf + OW_WIOU, g_bf + OW_WIOU + 81920, i);
        return;
    }
    i -= 32768;
    if (i < 49152) {
        int n = (int)(i >> 7), k = (int)(i & 127);
        wsplit(U_h[(long)k * 384 + n], g_bf + OW_WIOU + 32768, g_bf + OW_WIOU + 81920 + 32768, i);
        return;
    }
    i -= 49152;
    if (i < 640) {
        g_bio[i] = (i < 128) ? b_in[i] : (i < 256 ? b_out[i - 128] : 0.f);
        return;
    }
    i -= 640;
    if (i < 98304) {
        int n = (int)(i >> 8), k = (int)(i & 255);
        wsplit(W_a[(long)k * 384 + n], g_bf + OW_WA, g_bf + OW_WA + 98304, i);
        return;
    }
    i -= 98304;
    if (i < 49152) {
        int n = (int)(i >> 7), k = (int)(i & 127);
        wsplit(Wi[(long)k * 384 + n], g_bf + OW_WI, g_bf + OW_WI + 49152, i);
        return;
    }
    i -= 49152;
    if (i < 49152) {
        int n = (int)(i >> 7), k = (int)(i & 127);
        wsplit(Wh[(long)k * 384 + n], g_bf + OW_WH, g_bf + OW_WH + 49152, i);
        return;
    }
    i -= 49152;
    if (i < 16384) {
        int n = (int)(i >> 7), k = (int)(i & 127);
        wsplit(W2[(long)k * 128 + n], g_bf + OW_W2, g_bf + OW_W2 + 16384, i);
        return;
    }
    i -= 16384;
    if (i < (long)ED) {                                 // emb -> fp16 single plane
        reinterpret_cast<__half*>(g_bf + BO_EBF)[i] = __float2half(emb[i]);
        return;
    }
    i -= (long)ED;
    if (i < (long)RD) {
        wsplit(inter[i], g_bf + BO_IEH, g_bf + BO_IEH + (long)RD, i);
        return;
    }
    i -= (long)RD;
    if (i < (long)RD) {
        int row = (int)(i >> 7), d = (int)(i & 127);
        wsplit(emb[(long)items[row] * D + d], g_bf + BO_GAH, g_bf + BO_GAL, i);
    }
}

// ================= adjacency =================
__global__ void __launch_bounds__(128) adj_kernel(const float* __restrict__ Ain, const float* __restrict__ Aout) {
    const float* hg = g_f + F_HG;
    const int b = blockIdx.x, d = threadIdx.x;
    __shared__ float sAi[L * L], sAo[L * L], shi[L * D], sho[L * D];
    const float* Aib = Ain + (long)b * L * L;
    const float* Aob = Aout + (long)b * L * L;
    for (int i = d; i < L * L; i += 128) { sAi[i] = Aib[i]; sAo[i] = Aob[i]; }
    for (int i = d; i < L * D; i += 128) {
        int m = i >> 7, dd = i & 127;
        long r = ((long)b * L + m) * 640;
        shi[i] = hg[r + dd];
        sho[i] = hg[r + 128 + dd];
    }
    __syncthreads();
    for (int l = 0; l < L; l++) {
        float si = 0.f, so = 0.f;
#pragma unroll 8
        for (int m = 0; m < L; m++) {
            si += sAi[l * L + m] * shi[m * D + d];
            so += sAo[l * L + m] * sho[m * D + d];
        }
        long o = ((long)b * L + l) * 256;
        wsplit(si, g_bf + BO_AH, g_bf + BO_AL, o + d);
        wsplit(so, g_bf + BO_AH, g_bf + BO_AL, o + 128 + d);
    }
}

// ================= GRU kernels =================
__global__ void __launch_bounds__(256) gru1_kernel(const int* __restrict__ items, const float* __restrict__ emb) {
    long i = (long)blockIdx.x * 256 + threadIdx.x;
    if (i >= (long)RD) return;
    int row = (int)(i >> 7), d = (int)(i & 127);
    const float* gi = g_f + F_GI + (long)row * 384;
    const float* gh = g_f + F_HG + (long)row * 640 + 256;
    float r = sigf(gi[d] + gh[d]);
    float z = sigf(gi[128 + d] + gh[128 + d]);
    float n = tanhf(gi[256 + d] + r * gh[256 + d]);
    float hp = emb[(long)items[row] * D + d];
    wsplit((1.f - z) * n + z * hp, g_bf + BO_ITH, g_bf + BO_ITL, i);
}

__global__ void __launch_bounds__(256) gru2_kernel(const float* __restrict__ inter) {
    long i = (long)blockIdx.x * 256 + threadIdx.x;
    if (i >= (long)RD) return;
    int row = (int)(i >> 7), d = (int)(i & 127);
    const float* gi = g_f + F_GI + (long)row * 384;
    const float* gh = g_f + F_HG + (long)row * 384;
    float r = sigf(gi[d] + gh[d]);
    float z = sigf(gi[128 + d] + gh[128 + d]);
    float n = tanhf(gi[256 + d] + r * gh[256 + d]);
    float v = (1.f - z) * n + z * inter[i];
    g_f[F_FIN + i] = v;
    wsplit(v, g_bf + BO_FNH, g_bf + BO_FNL, i);
}

// ================= attention readout =================
__global__ void __launch_bounds__(128) readout_kernel(
    const int* __restrict__ seq_len,
    const float* __restrict__ W1, const float* __restrict__ b1,
    const float* __restrict__ wq, const float* __restrict__ bq,
    const float* __restrict__ W3, const float* __restrict__ b3)
{
    const float* fin = g_f + F_FIN;
    const float* fW2 = g_f + F_FW2;
    const int b = blockIdx.x, d = threadIdx.x;
    __shared__ float svn[D], sg_sh[D], gmat[L * D], alpha[L];

    const int sl = seq_len[b];
    const float* finb = fin + (long)b * L * D;
    svn[d] = finb[(long)(sl - 1) * D + d];
    __syncthreads();

    float q = b1[d];
    for (int k = 0; k < D; k++) q += svn[k] * W1[k * D + d];

    const float* fW2b = fW2 + (long)b * L * D;
    for (int l = 0; l < L; l++)
        gmat[l * D + d] = sigf(q + fW2b[l * D + d]);
    __syncthreads();

    int w = d >> 5, lane = d & 31;
    for (int l = w; l < L; l += 4) {
        float p = 0.f;
        for (int kk = lane; kk < D; kk += 32) p += gmat[l * D + kk] * wq[kk];
#pragma unroll
        for (int off = 16; off; off >>= 1) p += __shfl_xor_sync(0xFFFFFFFFu, p, off);
        if (lane == 0) alpha[l] = p + bq[0];
    }
    __syncthreads();

    float sg = 0.f;
    for (int l = 0; l < sl; l++) sg += alpha[l] * finb[(long)l * D + d];
    sg_sh[d] = sg;
    __syncthreads();

    float o = b3[d];
    for (int k = 0; k < D; k++) {
        o += svn[k]   * W3[k * D + d];
        o += sg_sh[k] * W3[(D + k) * D + d];
    }
    reinterpret_cast<__half*>(g_bf + BO_HSF)[(long)b * D + d] = __float2half(o);
}

// ================= launcher =================
extern "C" void kernel_launch(void* const* d_in, const int* in_sizes, int n_in,
                              void* d_out, int out_size)
{
    const int*   items  = (const int*)d_in[0];
    const float* A_in   = (const float*)d_in[1];
    const float* A_out  = (const float*)d_in[2];
    const float* inter  = (const float*)d_in[3];
    const int*   seqlen = (const int*)d_in[4];
    const float* emb    = (const float*)d_in[5];
    const float* W_in   = (const float*)d_in[6];
    const float* b_in   = (const float*)d_in[7];
    const float* W_out  = (const float*)d_in[8];
    const float* b_out  = (const float*)d_in[9];
    const float* W_a    = (const float*)d_in[10];
    const float* U_h    = (const float*)d_in[11];
    const float* b_gru  = (const float*)d_in[12];
    const float* Wi     = (const float*)d_in[13];
    const float* bi     = (const float*)d_in[14];
    const float* Wh     = (const float*)d_in[15];
    const float* bh     = (const float*)d_in[16];
    const float* W1     = (const float*)d_in[17];
    const float* b1     = (const float*)d_in[18];
    const float* W2     = (const float*)d_in[19];
    const float* b2     = (const float*)d_in[20];
    const float* wq     = (const float*)d_in[21];
    const float* bq     = (const float*)d_in[22];
    const float* W3     = (const float*)d_in[23];
    const float* b3     = (const float*)d_in[24];
    float* scores = (float*)d_out;

    cudaFuncSetAttribute(gemm_mma, cudaFuncAttributeMaxDynamicSharedMemorySize, GEMM_SMEM);

    const int MT = ROWS / 128;   // 256 M-tiles

    prep_all<<<(int)((PREP_TOTAL + 255) / 256), 256>>>(W_in, b_in, W_out, b_out, W_a, U_h,
                                                       Wi, Wh, W2, emb, inter, items);
    // [hio | gh] = gathered @ [W_in|W_out|U_h] + [bio|0]   (N=640, K=128)
    gemm_mma<<<dim3(MT, 5), 256, GEMM_SMEM>>>(BO_GAH, BO_GAL, OW_WIOU, OW_WIOU + 81920,
                                              nullptr, 2, nullptr, F_HG, 640, 128);
    adj_kernel<<<BATCH, 128>>>(A_in, A_out);
    gemm_mma<<<dim3(MT, 3), 256, GEMM_SMEM>>>(BO_AH, BO_AL, OW_WA, OW_WA + 98304,
                                              b_gru, 1, nullptr, F_GI, 384, 256);
    gru1_kernel<<<(RD + 255) / 256, 256>>>(items, emb);
    gemm_mma<<<dim3(MT, 3), 256, GEMM_SMEM>>>(BO_ITH, BO_ITL, OW_WI, OW_WI + 49152,
                                              bi, 1, nullptr, F_GI, 384, 128);
    gemm_mma<<<dim3(MT, 3), 256, GEMM_SMEM>>>(BO_IEH, BO_IEL, OW_WH, OW_WH + 49152,
                                              bh, 1, nullptr, F_HG, 384, 128);
    gru2_kernel<<<(RD + 255) / 256, 256>>>(inter);
    gemm_mma<<<dim3(MT, 1), 256, GEMM_SMEM>>>(BO_FNH, BO_FNL, OW_W2, OW_W2 + 16384,
                                              b2, 1, nullptr, F_FW2, 128, 128);
    readout_kernel<<<BATCH, 128>>>(seqlen, W1, b1, wq, bq, W3, b3);
    // scores = hs @ emb^T, single-pass fp16
    gemm_f16<<<dim3(BATCH / 128, (NNODE + 63) / 64), 256, F16_SMEM>>>(
        BO_HSF, BO_EBF, scores, NNODE, 128);
}

// round 12
// speedup vs baseline: 1.3528x; 1.2210x over previous
#include <cuda_runtime.h>
#include <cuda_fp16.h>
#include <math.h>
#include <cstdint>

#define BATCH 1024
#define L 32
#define D 128
#define NNODE 50000
#define ROWS (BATCH * L)           // 32768
#define RD   (ROWS * D)            // 4194304
#define BD   (BATCH * D)           // 131072
#define ED   (NNODE * D)           // 6400000

// ---------------- float scratch ----------------
#define F_HG   0L                   // [ROWS, 640] = hin|hout|gh(384); later [ROWS,384] gh2
#define F_GI   (5L * RD)            // [ROWS, 384]
#define F_FW2  (8L * RD)
#define F_FIN  (9L * RD)
#define F_TOTAL (10L * RD)
__device__ float g_f[F_TOTAL];
__device__ float g_bio[640];        // concat(b_in, b_out, zeros[384])

// ---------------- fp16 planes ----------------
#define H_GA   0L                   // gathered emb [ROWS,128]
#define H_A    ((long)RD)           // concat a [ROWS,256]
#define H_IT   (3L * RD)            // intra [ROWS,128]
#define H_FN   (4L * RD)            // final [ROWS,128]
#define H_IE   (5L * RD)            // inter [ROWS,128]
#define H_HS   (6L * RD)            // hs [1024,128]
#define H_EB   (6L * RD + BD)       // emb [50000,128]
#define HW_WIOU (6L * RD + BD + (long)ED)   // [640,128]
#define HW_WA   (HW_WIOU + 81920L)          // [384,256]
#define HW_WI   (HW_WA + 98304L)            // [384,128]
#define HW_WH   (HW_WI + 49152L)
#define HW_W2   (HW_WH + 49152L)            // [128,128]
#define H_TOTAL (HW_W2 + 16384L)
__device__ __half g_h[H_TOTAL];

// ---------------- helpers ----------------
__device__ __forceinline__ uint32_t smem_u32(const void* p) {
    uint32_t a;
    asm("{ .reg .u64 t; cvta.to.shared.u64 t, %1; cvt.u32.u64 %0, t; }" : "=r"(a) : "l"(p));
    return a;
}
__device__ __forceinline__ float sigf(float x) { return 1.0f / (1.0f + expf(-x)); }

__device__ __forceinline__ void mma_f16(float* d, const uint32_t* a, const uint32_t* b) {
    asm volatile(
        "mma.sync.aligned.m16n8k16.row.col.f32.f16.f16.f32 "
        "{%0,%1,%2,%3}, {%4,%5,%6,%7}, {%8,%9}, {%0,%1,%2,%3};"
        : "+f"(d[0]), "+f"(d[1]), "+f"(d[2]), "+f"(d[3])
        : "r"(a[0]), "r"(a[1]), "r"(a[2]), "r"(a[3]), "r"(b[0]), "r"(b[1]));
}
__device__ __forceinline__ void ldsm4(uint32_t* r, uint32_t a) {
    asm volatile("ldmatrix.sync.aligned.m8n8.x4.shared.b16 {%0,%1,%2,%3}, [%4];"
        : "=r"(r[0]), "=r"(r[1]), "=r"(r[2]), "=r"(r[3]) : "r"(a));
}

// ================= unified single-pass fp16 tensor-core GEMM =================
// C[M,N] = A[M,K] @ B[N,K]^T (+bias), fp16 inputs, fp32 accum.
// Block 128x64, 8 warps (4m x 2n), warp tile 32x32, K-chunk 32, 3 CTAs/SM.
// SMEM row stride 40 halfs (80B) -> conflict-free LDSM (proven layout).
#define APLB (128 * 80)
#define BPLB (64 * 80)
#define STAGEB (APLB + BPLB)        // 15360
#define GEMM_SMEM (2 * STAGEB)      // 30720

__global__ void __launch_bounds__(256, 3) gemm_f16(
    long a_off, long b_off,
    const float* __restrict__ bias_ext, int bias_mode,
    float* __restrict__ C_ext, long c_off, int N, int K)
{
    extern __shared__ __align__(16) char dsm[];
    const __half* A = g_h + a_off;
    const __half* B = g_h + b_off;
    float* C = C_ext ? C_ext : (g_f + c_off);
    const float* bias = (bias_mode == 1) ? bias_ext : (bias_mode == 2 ? g_bio : nullptr);

    const int tid = threadIdx.x;
    const int warp = tid >> 5, lane = tid & 31;
    const int wm = warp >> 1, wn = warp & 1;          // 4m x 2n
    const int g = lane >> 2, tig = lane & 3;

    const long bm = (long)blockIdx.x * 128;
    const int bn = blockIdx.y * 64;
    const int nsize = min(64, N - bn);

    const int fr = tid >> 1;
    const int fc = (tid & 1) * 16;
    const int br = tid >> 2;
    const int bq = (tid & 3) * 8;
    const long arow = bm + fr;
    const long brow = bn + (br < nsize ? br : 0);
    const int bok = (br < nsize) ? 16 : 0;
    const uint32_t smb = smem_u32(dsm);
    const uint32_t doffA = (uint32_t)(fr * 80 + fc * 2);
    const uint32_t doffB = (uint32_t)(br * 80 + bq * 2);

    const uint32_t laneA = (uint32_t)(((lane & 7) + (((lane >> 3) & 1) << 3)) * 80 + (lane >> 4) * 16);
    const uint32_t laneB = (uint32_t)(((lane & 7) + ((lane >> 4) << 3)) * 80 + ((lane >> 3) & 1) * 16);
    const uint32_t aBaseA = (uint32_t)(wm * 32 * 80) + laneA;
    const uint32_t aBaseB = (uint32_t)(wn * 32 * 80) + laneB;

    float acc[2][4][4];
#pragma unroll
    for (int i = 0; i < 2; i++)
#pragma unroll
        for (int j = 0; j < 4; j++)
#pragma unroll
            for (int v = 0; v < 4; v++) acc[i][j][v] = 0.f;

#define LOADF(c_, st_) do {                                                            \
    const long k0_ = (long)(c_) * 32;                                                  \
    const uint32_t b_ = smb + (uint32_t)(st_) * STAGEB;                                \
    const __half* pa_ = A + arow * K + k0_ + fc;                                       \
    const __half* pb_ = B + brow * K + k0_ + bq;                                       \
    asm volatile("cp.async.cg.shared.global [%0], [%1], 16;" :: "r"(b_ + doffA), "l"(pa_)); \
    asm volatile("cp.async.cg.shared.global [%0], [%1], 16;" :: "r"(b_ + doffA + 16), "l"(pa_ + 8)); \
    asm volatile("cp.async.cg.shared.global [%0], [%1], 16, %2;" :: "r"(b_ + APLB + doffB), "l"(pb_), "r"(bok)); \
    asm volatile("cp.async.commit_group;");                                            \
} while (0)

    const int nch = K / 32;
    LOADF(0, 0);
    for (int c = 0; c < nch; c++) {
        const int st = c & 1;
        asm volatile("cp.async.wait_group 0;");
        __syncthreads();
        if (c + 1 < nch) LOADF(c + 1, st ^ 1);

        const uint32_t stb = smb + (uint32_t)st * STAGEB;
        const uint32_t pA = stb + aBaseA;
        const uint32_t pB = stb + APLB + aBaseB;

#pragma unroll
        for (int ks = 0; ks < 2; ks++) {
            const uint32_t ko = (uint32_t)(ks * 32);
            uint32_t af[2][4], bf[4][2];
#pragma unroll
            for (int mf = 0; mf < 2; mf++)
                ldsm4(af[mf], pA + (uint32_t)(mf * 16 * 80) + ko);
#pragma unroll
            for (int np = 0; np < 2; np++) {
                uint32_t bt[4];
                ldsm4(bt, pB + (uint32_t)(np * 16 * 80) + ko);
                bf[np * 2][0] = bt[0]; bf[np * 2][1] = bt[1];
                bf[np * 2 + 1][0] = bt[2]; bf[np * 2 + 1][1] = bt[3];
            }
#pragma unroll
            for (int mf = 0; mf < 2; mf++)
#pragma unroll
                for (int nf = 0; nf < 4; nf++)
                    mma_f16(acc[mf][nf], af[mf], bf[nf]);
        }
    }

#pragma unroll
    for (int mf = 0; mf < 2; mf++) {
        const long row = bm + wm * 32 + mf * 16 + g;
#pragma unroll
        for (int nf = 0; nf < 4; nf++) {
            const int col = bn + wn * 32 + nf * 8 + tig * 2;
            if (col < N) {
                float bx = bias ? bias[col] : 0.f;
                float by = bias ? bias[col + 1] : 0.f;
                *(float2*)&C[row * N + col] =
                    make_float2(acc[mf][nf][0] + bx, acc[mf][nf][1] + by);
                *(float2*)&C[(row + 8) * N + col] =
                    make_float2(acc[mf][nf][2] + bx, acc[mf][nf][3] + by);
            }
        }
    }
#undef LOADF
}

// ================= fused prep =================
// ranges: Wio 32768 | Uh 49152 | bio 640 | Wa 98304 | Wi 49152 | Wh 49152 |
//         W2 16384 | emb ED | inter RD | gather RD
#define PREP_TOTAL (32768L + 49152 + 640 + 98304 + 49152 + 49152 + 16384 + (long)ED + 2L * RD)
__global__ void __launch_bounds__(256) prep_all(
    const float* __restrict__ W_in, const float* __restrict__ b_in,
    const float* __restrict__ W_out, const float* __restrict__ b_out,
    const float* __restrict__ W_a, const float* __restrict__ U_h,
    const float* __restrict__ Wi, const float* __restrict__ Wh,
    const float* __restrict__ W2,
    const float* __restrict__ emb, const float* __restrict__ inter,
    const int* __restrict__ items)
{
    long i = (long)blockIdx.x * 256 + threadIdx.x;
    if (i < 32768) {                                    // Wio rows 0..255 of [640,128]
        int n = (int)(i >> 7), k = (int)(i & 127);
        float v = (n < 128) ? W_in[k * 128 + n] : W_out[k * 128 + (n - 128)];
        g_h[HW_WIOU + i] = __float2half(v);
        return;
    }
    i -= 32768;
    if (i < 49152) {                                    // U_h rows 256..639
        int n = (int)(i >> 7), k = (int)(i & 127);
        g_h[HW_WIOU + 32768 + i] = __float2half(U_h[(long)k * 384 + n]);
        return;
    }
    i -= 49152;
    if (i < 640) {
        g_bio[i] = (i < 128) ? b_in[i] : (i < 256 ? b_out[i - 128] : 0.f);
        return;
    }
    i -= 640;
    if (i < 98304) {                                    // W_a [384,256]
        int n = (int)(i >> 8), k = (int)(i & 255);
        g_h[HW_WA + i] = __float2half(W_a[(long)k * 384 + n]);
        return;
    }
    i -= 98304;
    if (i < 49152) {                                    // Wi [384,128]
        int n = (int)(i >> 7), k = (int)(i & 127);
        g_h[HW_WI + i] = __float2half(Wi[(long)k * 384 + n]);
        return;
    }
    i -= 49152;
    if (i < 49152) {                                    // Wh [384,128]
        int n = (int)(i >> 7), k = (int)(i & 127);
        g_h[HW_WH + i] = __float2half(Wh[(long)k * 384 + n]);
        return;
    }
    i -= 49152;
    if (i < 16384) {                                    // W2 [128,128]
        int n = (int)(i >> 7), k = (int)(i & 127);
        g_h[HW_W2 + i] = __float2half(W2[(long)k * 128 + n]);
        return;
    }
    i -= 16384;
    if (i < (long)ED) {                                 // emb -> fp16
        g_h[H_EB + i] = __float2half(emb[i]);
        return;
    }
    i -= (long)ED;
    if (i < (long)RD) {                                 // inter -> fp16
        g_h[H_IE + i] = __float2half(inter[i]);
        return;
    }
    i -= (long)RD;
    if (i < (long)RD) {                                 // gather emb[items] -> fp16
        int row = (int)(i >> 7), d = (int)(i & 127);
        g_h[H_GA + i] = __float2half(emb[(long)items[row] * D + d]);
    }
}

// ================= adjacency (hio from [ROWS,640] cols 0..255) =================
__global__ void __launch_bounds__(128) adj_kernel(const float* __restrict__ Ain, const float* __restrict__ Aout) {
    const float* hg = g_f + F_HG;
    const int b = blockIdx.x, d = threadIdx.x;
    __shared__ float sAi[L * L], sAo[L * L], shi[L * D], sho[L * D];
    const float* Aib = Ain + (long)b * L * L;
    const float* Aob = Aout + (long)b * L * L;
    for (int i = d; i < L * L; i += 128) { sAi[i] = Aib[i]; sAo[i] = Aob[i]; }
    for (int i = d; i < L * D; i += 128) {
        int m = i >> 7, dd = i & 127;
        long r = ((long)b * L + m) * 640;
        shi[i] = hg[r + dd];
        sho[i] = hg[r + 128 + dd];
    }
    __syncthreads();
    for (int l = 0; l < L; l++) {
        float si = 0.f, so = 0.f;
#pragma unroll 8
        for (int m = 0; m < L; m++) {
            si += sAi[l * L + m] * shi[m * D + d];
            so += sAo[l * L + m] * sho[m * D + d];
        }
        long o = ((long)b * L + l) * 256;
        g_h[H_A + o + d]       = __float2half(si);
        g_h[H_A + o + 128 + d] = __float2half(so);
    }
}

// ================= GRU kernels =================
// GRU1: gi [ROWS,384] @ F_GI; gh = cols 256..639 of [ROWS,640] @ F_HG
__global__ void __launch_bounds__(256) gru1_kernel(const int* __restrict__ items, const float* __restrict__ emb) {
    long i = (long)blockIdx.x * 256 + threadIdx.x;
    if (i >= (long)RD) return;
    int row = (int)(i >> 7), d = (int)(i & 127);
    const float* gi = g_f + F_GI + (long)row * 384;
    const float* gh = g_f + F_HG + (long)row * 640 + 256;
    float r = sigf(gi[d] + gh[d]);
    float z = sigf(gi[128 + d] + gh[128 + d]);
    float n = tanhf(gi[256 + d] + r * gh[256 + d]);
    float hp = emb[(long)items[row] * D + d];
    g_h[H_IT + i] = __float2half((1.f - z) * n + z * hp);
}

// GRU2: gi [ROWS,384] @ F_GI; gh [ROWS,384] @ F_HG
__global__ void __launch_bounds__(256) gru2_kernel(const float* __restrict__ inter) {
    long i = (long)blockIdx.x * 256 + threadIdx.x;
    if (i >= (long)RD) return;
    int row = (int)(i >> 7), d = (int)(i & 127);
    const float* gi = g_f + F_GI + (long)row * 384;
    const float* gh = g_f + F_HG + (long)row * 384;
    float r = sigf(gi[d] + gh[d]);
    float z = sigf(gi[128 + d] + gh[128 + d]);
    float n = tanhf(gi[256 + d] + r * gh[256 + d]);
    float v = (1.f - z) * n + z * inter[i];
    g_f[F_FIN + i] = v;
    g_h[H_FN + i] = __float2half(v);
}

// ================= attention readout =================
__global__ void __launch_bounds__(128) readout_kernel(
    const int* __restrict__ seq_len,
    const float* __restrict__ W1, const float* __restrict__ b1,
    const float* __restrict__ wq, const float* __restrict__ bq,
    const float* __restrict__ W3, const float* __restrict__ b3)
{
    const float* fin = g_f + F_FIN;
    const float* fW2 = g_f + F_FW2;
    const int b = blockIdx.x, d = threadIdx.x;
    __shared__ float svn[D], sg_sh[D], gmat[L * D], alpha[L];

    const int sl = seq_len[b];
    const float* finb = fin + (long)b * L * D;
    svn[d] = finb[(long)(sl - 1) * D + d];
    __syncthreads();

    float q = b1[d];
    for (int k = 0; k < D; k++) q += svn[k] * W1[k * D + d];

    const float* fW2b = fW2 + (long)b * L * D;
    for (int l = 0; l < L; l++)
        gmat[l * D + d] = sigf(q + fW2b[l * D + d]);
    __syncthreads();

    int w = d >> 5, lane = d & 31;
    for (int l = w; l < L; l += 4) {
        float p = 0.f;
        for (int kk = lane; kk < D; kk += 32) p += gmat[l * D + kk] * wq[kk];
#pragma unroll
        for (int off = 16; off; off >>= 1) p += __shfl_xor_sync(0xFFFFFFFFu, p, off);
        if (lane == 0) alpha[l] = p + bq[0];
    }
    __syncthreads();

    float sg = 0.f;
    for (int l = 0; l < sl; l++) sg += alpha[l] * finb[(long)l * D + d];
    sg_sh[d] = sg;
    __syncthreads();

    float o = b3[d];
    for (int k = 0; k < D; k++) {
        o += svn[k]   * W3[k * D + d];
        o += sg_sh[k] * W3[(D + k) * D + d];
    }
    g_h[H_HS + (long)b * D + d] = __float2half(o);
}

// ================= launcher: pure kernel launches =================
extern "C" void kernel_launch(void* const* d_in, const int* in_sizes, int n_in,
                              void* d_out, int out_size)
{
    const int*   items  = (const int*)d_in[0];
    const float* A_in   = (const float*)d_in[1];
    const float* A_out  = (const float*)d_in[2];
    const float* inter  = (const float*)d_in[3];
    const int*   seqlen = (const int*)d_in[4];
    const float* emb    = (const float*)d_in[5];
    const float* W_in   = (const float*)d_in[6];
    const float* b_in   = (const float*)d_in[7];
    const float* W_out  = (const float*)d_in[8];
    const float* b_out  = (const float*)d_in[9];
    const float* W_a    = (const float*)d_in[10];
    const float* U_h    = (const float*)d_in[11];
    const float* b_gru  = (const float*)d_in[12];
    const float* Wi     = (const float*)d_in[13];
    const float* bi     = (const float*)d_in[14];
    const float* Wh     = (const float*)d_in[15];
    const float* bh     = (const float*)d_in[16];
    const float* W1     = (const float*)d_in[17];
    const float* b1     = (const float*)d_in[18];
    const float* W2     = (const float*)d_in[19];
    const float* b2     = (const float*)d_in[20];
    const float* wq     = (const float*)d_in[21];
    const float* bq     = (const float*)d_in[22];
    const float* W3     = (const float*)d_in[23];
    const float* b3     = (const float*)d_in[24];
    float* scores = (float*)d_out;

    const int MT = ROWS / 128;   // 256 M-tiles

    prep_all<<<(int)((PREP_TOTAL + 255) / 256), 256>>>(W_in, b_in, W_out, b_out, W_a, U_h,
                                                       Wi, Wh, W2, emb, inter, items);
    // [hio | gh] = gathered @ [W_in|W_out|U_h] + [bio|0]   (N=640, K=128)
    gemm_f16<<<dim3(MT, 10), 256, GEMM_SMEM>>>(H_GA, HW_WIOU, nullptr, 2, nullptr, F_HG, 640, 128);
    adj_kernel<<<BATCH, 128>>>(A_in, A_out);
    gemm_f16<<<dim3(MT, 6), 256, GEMM_SMEM>>>(H_A, HW_WA, b_gru, 1, nullptr, F_GI, 384, 256);
    gru1_kernel<<<(RD + 255) / 256, 256>>>(items, emb);
    gemm_f16<<<dim3(MT, 6), 256, GEMM_SMEM>>>(H_IT, HW_WI, bi, 1, nullptr, F_GI, 384, 128);
    gemm_f16<<<dim3(MT, 6), 256, GEMM_SMEM>>>(H_IE, HW_WH, bh, 1, nullptr, F_HG, 384, 128);
    gru2_kernel<<<(RD + 255) / 256, 256>>>(inter);
    gemm_f16<<<dim3(MT, 2), 256, GEMM_SMEM>>>(H_FN, HW_W2, b2, 1, nullptr, F_FW2, 128, 128);
    readout_kernel<<<BATCH, 128>>>(seqlen, W1, b1, wq, bq, W3, b3);
    // scores = hs @ emb^T
    gemm_f16<<<dim3(BATCH / 128, (NNODE + 63) / 64), 256, GEMM_SMEM>>>(
        H_HS, H_EB, nullptr, 0, scores, 0, NNODE, 128);
}

// round 14
// speedup vs baseline: 1.4153x; 1.0462x over previous
#include <cuda_runtime.h>
#include <cuda_fp16.h>
#include <math.h>
#include <cstdint>

#define BATCH 1024
#define L 32
#define D 128
#define NNODE 50000
#define ROWS (BATCH * L)           // 32768
#define RD   (ROWS * D)            // 4194304
#define BD   (BATCH * D)           // 131072
#define ED   (NNODE * D)           // 6400000

// ---------------- float scratch (final only) ----------------
#define F_FIN  0L
__device__ float g_f[RD];
__device__ float g_bio[640];        // concat(b_in, b_out, zeros[384])

// ---------------- fp16 planes ----------------
#define H_GA   0L                   // gathered emb [ROWS,128]
#define H_A    ((long)RD)           // concat a [ROWS,256]
#define H_IT   (3L * RD)            // intra [ROWS,128]
#define H_FN   (4L * RD)            // final fp16 [ROWS,128]
#define H_IE   (5L * RD)            // inter [ROWS,128]
#define H_HG   (6L * RD)            // [ROWS,640] hin|hout|gh; later [ROWS,384] gh2
#define H_GI   (11L * RD)           // [ROWS,384]
#define H_FW2  (14L * RD)           // [ROWS,128]
#define H_HS   (15L * RD)           // [1024,128]
#define H_EB   (15L * RD + BD)      // emb [50000,128]
#define HW_WIOU (15L * RD + BD + (long)ED)  // [640,128]
#define HW_WA   (HW_WIOU + 81920L)          // [384,256]
#define HW_WI   (HW_WA + 98304L)            // [384,128]
#define HW_WH   (HW_WI + 49152L)
#define HW_W2   (HW_WH + 49152L)            // [128,128]
#define H_TOTAL (HW_W2 + 16384L)
__device__ __half g_h[H_TOTAL];

// ---------------- helpers ----------------
__device__ __forceinline__ uint32_t smem_u32(const void* p) {
    uint32_t a;
    asm("{ .reg .u64 t; cvta.to.shared.u64 t, %1; cvt.u32.u64 %0, t; }" : "=r"(a) : "l"(p));
    return a;
}
__device__ __forceinline__ float sigf(float x) { return 1.0f / (1.0f + expf(-x)); }

__device__ __forceinline__ void mma_f16(float* d, const uint32_t* a, const uint32_t* b) {
    asm volatile(
        "mma.sync.aligned.m16n8k16.row.col.f32.f16.f16.f32 "
        "{%0,%1,%2,%3}, {%4,%5,%6,%7}, {%8,%9}, {%0,%1,%2,%3};"
        : "+f"(d[0]), "+f"(d[1]), "+f"(d[2]), "+f"(d[3])
        : "r"(a[0]), "r"(a[1]), "r"(a[2]), "r"(a[3]), "r"(b[0]), "r"(b[1]));
}
__device__ __forceinline__ void ldsm4(uint32_t* r, uint32_t a) {
    asm volatile("ldmatrix.sync.aligned.m8n8.x4.shared.b16 {%0,%1,%2,%3}, [%4];"
        : "=r"(r[0]), "=r"(r[1]), "=r"(r[2]), "=r"(r[3]) : "r"(a));
}

// ================= single-pass fp16 GEMM, 128x128 tile =================
// C[M,N] = A[M,K] @ B[N,K]^T (+bias). fp32 accum.
// Block 128x128, 8 warps (2m x 4n), warp tile 64x32, K-chunk 32, 2 CTAs/SM.
// Output: fp16 to g_h+ch_off (Cf==null) or fp32 to Cf (scores).
// SMEM row stride 40 halfs (80B) -> conflict-free LDSM (proven layout).
#define APLB (128 * 80)
#define BPLB (128 * 80)
#define STAGEB (APLB + BPLB)        // 20480
#define GEMM_SMEM (2 * STAGEB)      // 40960

__global__ void __launch_bounds__(256, 2) gemm_f16(
    long a_off, long b_off,
    const float* __restrict__ bias_ext, int bias_mode,
    float* __restrict__ Cf, long ch_off, int N, int K)
{
    extern __shared__ __align__(16) char dsm[];
    const __half* A = g_h + a_off;
    const __half* B = g_h + b_off;
    const float* bias = (bias_mode == 1) ? bias_ext : (bias_mode == 2 ? g_bio : nullptr);

    const int tid = threadIdx.x;
    const int warp = tid >> 5, lane = tid & 31;
    const int wm = warp & 1, wn = warp >> 1;          // 2m x 4n
    const int g = lane >> 2, tig = lane & 3;

    const long bm = (long)blockIdx.x * 128;
    const int bn = blockIdx.y * 128;
    const int nsize = min(128, N - bn);

    const int fr = tid >> 1;
    const int fc = (tid & 1) * 16;
    const long arow = bm + fr;
    const long brow = bn + (fr < nsize ? fr : 0);
    const int bok = (fr < nsize) ? 16 : 0;
    const uint32_t smb = smem_u32(dsm);
    const uint32_t doff = (uint32_t)(fr * 80 + fc * 2);

    const uint32_t laneA = (uint32_t)(((lane & 7) + (((lane >> 3) & 1) << 3)) * 80 + (lane >> 4) * 16);
    const uint32_t laneB = (uint32_t)(((lane & 7) + ((lane >> 4) << 3)) * 80 + ((lane >> 3) & 1) * 16);
    const uint32_t aBaseA = (uint32_t)(wm * 64 * 80) + laneA;
    const uint32_t aBaseB = (uint32_t)(wn * 32 * 80) + laneB;

    float acc[4][4][4];
#pragma unroll
    for (int i = 0; i < 4; i++)
#pragma unroll
        for (int j = 0; j < 4; j++)
#pragma unroll
            for (int v = 0; v < 4; v++) acc[i][j][v] = 0.f;

#define LOADF(c_, st_) do {                                                            \
    const long k0_ = (long)(c_) * 32;                                                  \
    const uint32_t b_ = smb + (uint32_t)(st_) * STAGEB;                                \
    const __half* pa_ = A + arow * K + k0_ + fc;                                       \
    const __half* pb_ = B + brow * K + k0_ + fc;                                       \
    asm volatile("cp.async.cg.shared.global [%0], [%1], 16;" :: "r"(b_ + doff), "l"(pa_)); \
    asm volatile("cp.async.cg.shared.global [%0], [%1], 16;" :: "r"(b_ + doff + 16), "l"(pa_ + 8)); \
    asm volatile("cp.async.cg.shared.global [%0], [%1], 16, %2;" :: "r"(b_ + APLB + doff), "l"(pb_), "r"(bok)); \
    asm volatile("cp.async.cg.shared.global [%0], [%1], 16, %2;" :: "r"(b_ + APLB + doff + 16), "l"(pb_ + 8), "r"(bok)); \
    asm volatile("cp.async.commit_group;");                                            \
} while (0)

    const int nch = K / 32;
    LOADF(0, 0);
    for (int c = 0; c < nch; c++) {
        const int st = c & 1;
        asm volatile("cp.async.wait_group 0;");
        __syncthreads();
        if (c + 1 < nch) LOADF(c + 1, st ^ 1);

        const uint32_t stb = smb + (uint32_t)st * STAGEB;
        const uint32_t pA = stb + aBaseA;
        const uint32_t pB = stb + APLB + aBaseB;

#pragma unroll
        for (int ks = 0; ks < 2; ks++) {
            const uint32_t ko = (uint32_t)(ks * 32);
            uint32_t af[4][4], bf[4][2];
#pragma unroll
            for (int mf = 0; mf < 4; mf++)
                ldsm4(af[mf], pA + (uint32_t)(mf * 16 * 80) + ko);
#pragma unroll
            for (int np = 0; np < 2; np++) {
                uint32_t bt[4];
                ldsm4(bt, pB + (uint32_t)(np * 16 * 80) + ko);
                bf[np * 2][0] = bt[0]; bf[np * 2][1] = bt[1];
                bf[np * 2 + 1][0] = bt[2]; bf[np * 2 + 1][1] = bt[3];
            }
#pragma unroll
            for (int mf = 0; mf < 4; mf++)
#pragma unroll
                for (int nf = 0; nf < 4; nf++)
                    mma_f16(acc[mf][nf], af[mf], bf[nf]);
        }
    }

    __half* Ch = g_h + ch_off;
#pragma unroll
    for (int mf = 0; mf < 4; mf++) {
        const long row = bm + wm * 64 + mf * 16 + g;
#pragma unroll
        for (int nf = 0; nf < 4; nf++) {
            const int col = bn + wn * 32 + nf * 8 + tig * 2;
            if (col < N) {
                float bx = bias ? bias[col] : 0.f;
                float by = bias ? bias[col + 1] : 0.f;
                float v0 = acc[mf][nf][0] + bx, v1 = acc[mf][nf][1] + by;
                float v2 = acc[mf][nf][2] + bx, v3 = acc[mf][nf][3] + by;
                if (Cf) {
                    *(float2*)&Cf[row * N + col]       = make_float2(v0, v1);
                    *(float2*)&Cf[(row + 8) * N + col] = make_float2(v2, v3);
                } else {
                    *(__half2*)&Ch[row * N + col]       = __floats2half2_rn(v0, v1);
                    *(__half2*)&Ch[(row + 8) * N + col] = __floats2half2_rn(v2, v3);
                }
            }
        }
    }
#undef LOADF
}

// ================= fused prep =================
#define PREP_TOTAL (32768L + 49152 + 640 + 98304 + 49152 + 49152 + 16384 + (long)ED + 2L * RD)
__global__ void __launch_bounds__(256) prep_all(
    const float* __restrict__ W_in, const float* __restrict__ b_in,
    const float* __restrict__ W_out, const float* __restrict__ b_out,
    const float* __restrict__ W_a, const float* __restrict__ U_h,
    const float* __restrict__ Wi, const float* __restrict__ Wh,
    const float* __restrict__ W2,
    const float* __restrict__ emb, const float* __restrict__ inter,
    const int* __restrict__ items)
{
    long i = (long)blockIdx.x * 256 + threadIdx.x;
    if (i < 32768) {                                    // Wio rows 0..255 of [640,128]
        int n = (int)(i >> 7), k = (int)(i & 127);
        float v = (n < 128) ? W_in[k * 128 + n] : W_out[k * 128 + (n - 128)];
        g_h[HW_WIOU + i] = __float2half(v);
        return;
    }
    i -= 32768;
    if (i < 49152) {                                    // U_h rows 256..639
        int n = (int)(i >> 7), k = (int)(i & 127);
        g_h[HW_WIOU + 32768 + i] = __float2half(U_h[(long)k * 384 + n]);
        return;
    }
    i -= 49152;
    if (i < 640) {
        g_bio[i] = (i < 128) ? b_in[i] : (i < 256 ? b_out[i - 128] : 0.f);
        return;
    }
    i -= 640;
    if (i < 98304) {                                    // W_a [384,256]
        int n = (int)(i >> 8), k = (int)(i & 255);
        g_h[HW_WA + i] = __float2half(W_a[(long)k * 384 + n]);
        return;
    }
    i -= 98304;
    if (i < 49152) {                                    // Wi [384,128]
        int n = (int)(i >> 7), k = (int)(i & 127);
        g_h[HW_WI + i] = __float2half(Wi[(long)k * 384 + n]);
        return;
    }
    i -= 49152;
    if (i < 49152) {                                    // Wh [384,128]
        int n = (int)(i >> 7), k = (int)(i & 127);
        g_h[HW_WH + i] = __float2half(Wh[(long)k * 384 + n]);
        return;
    }
    i -= 49152;
    if (i < 16384) {                                    // W2 [128,128]
        int n = (int)(i >> 7), k = (int)(i & 127);
        g_h[HW_W2 + i] = __float2half(W2[(long)k * 128 + n]);
        return;
    }
    i -= 16384;
    if (i < (long)ED) {
        g_h[H_EB + i] = __float2half(emb[i]);
        return;
    }
    i -= (long)ED;
    if (i < (long)RD) {
        g_h[H_IE + i] = __float2half(inter[i]);
        return;
    }
    i -= (long)RD;
    if (i < (long)RD) {
        int row = (int)(i >> 7), d = (int)(i & 127);
        g_h[H_GA + i] = __float2half(emb[(long)items[row] * D + d]);
    }
}

// ================= adjacency (hio = cols 0..255 of fp16 [ROWS,640]) =============
__global__ void __launch_bounds__(128) adj_kernel(const float* __restrict__ Ain, const float* __restrict__ Aout) {
    const __half* hg = g_h + H_HG;
    const int b = blockIdx.x, d = threadIdx.x;
    __shared__ float sAi[L * L], sAo[L * L], shi[L * D], sho[L * D];
    const float* Aib = Ain + (long)b * L * L;
    const float* Aob = Aout + (long)b * L * L;
    for (int i = d; i < L * L; i += 128) { sAi[i] = Aib[i]; sAo[i] = Aob[i]; }
    for (int i = d; i < L * D; i += 128) {
        int m = i >> 7, dd = i & 127;
        long r = ((long)b * L + m) * 640;
        shi[i] = __half2float(hg[r + dd]);
        sho[i] = __half2float(hg[r + 128 + dd]);
    }
    __syncthreads();
    for (int l = 0; l < L; l++) {
        float si = 0.f, so = 0.f;
#pragma unroll 8
        for (int m = 0; m < L; m++) {
            si += sAi[l * L + m] * shi[m * D + d];
            so += sAo[l * L + m] * sho[m * D + d];
        }
        long o = ((long)b * L + l) * 256;
        g_h[H_A + o + d]       = __float2half(si);
        g_h[H_A + o + 128 + d] = __float2half(so);
    }
}

// ================= GRU kernels (fp16 gate inputs) =================
__global__ void __launch_bounds__(256) gru1_kernel(const int* __restrict__ items, const float* __restrict__ emb) {
    long i = (long)blockIdx.x * 256 + threadIdx.x;
    if (i >= (long)RD) return;
    int row = (int)(i >> 7), d = (int)(i & 127);
    const __half* gi = g_h + H_GI + (long)row * 384;
    const __half* gh = g_h + H_HG + (long)row * 640 + 256;
    float r = sigf(__half2float(gi[d]) + __half2float(gh[d]));
    float z = sigf(__half2float(gi[128 + d]) + __half2float(gh[128 + d]));
    float n = tanhf(__half2float(gi[256 + d]) + r * __half2float(gh[256 + d]));
    float hp = emb[(long)items[row] * D + d];
    g_h[H_IT + i] = __float2half((1.f - z) * n + z * hp);
}

__global__ void __launch_bounds__(256) gru2_kernel(const float* __restrict__ inter) {
    long i = (long)blockIdx.x * 256 + threadIdx.x;
    if (i >= (long)RD) return;
    int row = (int)(i >> 7), d = (int)(i & 127);
    const __half* gi = g_h + H_GI + (long)row * 384;
    const __half* gh = g_h + H_HG + (long)row * 384;
    float r = sigf(__half2float(gi[d]) + __half2float(gh[d]));
    float z = sigf(__half2float(gi[128 + d]) + __half2float(gh[128 + d]));
    float n = tanhf(__half2float(gi[256 + d]) + r * __half2float(gh[256 + d]));
    float v = (1.f - z) * n + z * inter[i];
    g_f[F_FIN + i] = v;
    g_h[H_FN + i] = __float2half(v);
}

// ================= attention readout =================
__global__ void __launch_bounds__(128) readout_kernel(
    const int* __restrict__ seq_len,
    const float* __restrict__ W1, const float* __restrict__ b1,
    const float* __restrict__ wq, const float* __restrict__ bq,
    const float* __restrict__ W3, const float* __restrict__ b3)
{
    const float* fin = g_f + F_FIN;
    const __half* fW2 = g_h + H_FW2;
    const int b = blockIdx.x, d = threadIdx.x;
    __shared__ float svn[D], sg_sh[D], gmat[L * D], alpha[L];

    const int sl = seq_len[b];
    const float* finb = fin + (long)b * L * D;
    svn[d] = finb[(long)(sl - 1) * D + d];
    __syncthreads();

    float q = b1[d];
    for (int k = 0; k < D; k++) q += svn[k] * W1[k * D + d];

    const __half* fW2b = fW2 + (long)b * L * D;
    for (int l = 0; l < L; l++)
        gmat[l * D + d] = sigf(q + __half2float(fW2b[l * D + d]));
    __syncthreads();

    int w = d >> 5, lane = d & 31;
    for (int l = w; l < L; l += 4) {
        float p = 0.f;
        for (int kk = lane; kk < D; kk += 32) p += gmat[l * D + kk] * wq[kk];
#pragma unroll
        for (int off = 16; off; off >>= 1) p += __shfl_xor_sync(0xFFFFFFFFu, p, off);
        if (lane == 0) alpha[l] = p + bq[0];
    }
    __syncthreads();

    float sg = 0.f;
    for (int l = 0; l < sl; l++) sg += alpha[l] * finb[(long)l * D + d];
    sg_sh[d] = sg;
    __syncthreads();

    float o = b3[d];
    for (int k = 0; k < D; k++) {
        o += svn[k]   * W3[k * D + d];
        o += sg_sh[k] * W3[(D + k) * D + d];
    }
    g_h[H_HS + (long)b * D + d] = __float2half(o);
}

// ================= launcher: pure kernel launches =================
extern "C" void kernel_launch(void* const* d_in, const int* in_sizes, int n_in,
                              void* d_out, int out_size)
{
    const int*   items  = (const int*)d_in[0];
    const float* A_in   = (const float*)d_in[1];
    const float* A_out  = (const float*)d_in[2];
    const float* inter  = (const float*)d_in[3];
    const int*   seqlen = (const int*)d_in[4];
    const float* emb    = (const float*)d_in[5];
    const float* W_in   = (const float*)d_in[6];
    const float* b_in   = (const float*)d_in[7];
    const float* W_out  = (const float*)d_in[8];
    const float* b_out  = (const float*)d_in[9];
    const float* W_a    = (const float*)d_in[10];
    const float* U_h    = (const float*)d_in[11];
    const float* b_gru  = (const float*)d_in[12];
    const float* Wi     = (const float*)d_in[13];
    const float* bi     = (const float*)d_in[14];
    const float* Wh     = (const float*)d_in[15];
    const float* bh     = (const float*)d_in[16];
    const float* W1     = (const float*)d_in[17];
    const float* b1     = (const float*)d_in[18];
    const float* W2     = (const float*)d_in[19];
    const float* b2     = (const float*)d_in[20];
    const float* wq     = (const float*)d_in[21];
    const float* bq     = (const float*)d_in[22];
    const float* W3     = (const float*)d_in[23];
    const float* b3     = (const float*)d_in[24];
    float* scores = (float*)d_out;

    const int MT = ROWS / 128;   // 256 M-tiles

    prep_all<<<(int)((PREP_TOTAL + 255) / 256), 256>>>(W_in, b_in, W_out, b_out, W_a, U_h,
                                                       Wi, Wh, W2, emb, inter, items);
    // [hio | gh] = gathered @ [W_in|W_out|U_h] + [bio|0]   (N=640, K=128)
    gemm_f16<<<dim3(MT, 5), 256, GEMM_SMEM>>>(H_GA, HW_WIOU, nullptr, 2, nullptr, H_HG, 640, 128);
    adj_kernel<<<BATCH, 128>>>(A_in, A_out);
    gemm_f16<<<dim3(MT, 3), 256, GEMM_SMEM>>>(H_A, HW_WA, b_gru, 1, nullptr, H_GI, 384, 256);
    gru1_kernel<<<(RD + 255) / 256, 256>>>(items, emb);
    gemm_f16<<<dim3(MT, 3), 256, GEMM_SMEM>>>(H_IT, HW_WI, bi, 1, nullptr, H_GI, 384, 128);
    gemm_f16<<<dim3(MT, 3), 256, GEMM_SMEM>>>(H_IE, HW_WH, bh, 1, nullptr, H_HG, 384, 128);
    gru2_kernel<<<(RD + 255) / 256, 256>>>(inter);
    gemm_f16<<<dim3(MT, 1), 256, GEMM_SMEM>>>(H_FN, HW_W2, b2, 1, nullptr, H_FW2, 128, 128);
    readout_kernel<<<BATCH, 128>>>(seqlen, W1, b1, wq, bq, W3, b3);
    // scores = hs @ emb^T  (fp32 output to d_out)
    gemm_f16<<<dim3(BATCH / 128, (NNODE + 127) / 128), 256, GEMM_SMEM>>>(
        H_HS, H_EB, nullptr, 0, scores, 0, NNODE, 128);
}

// round 16
// speedup vs baseline: 1.4645x; 1.0348x over previous
#include <cuda_runtime.h>
#include <cuda_fp16.h>
#include <math.h>
#include <cstdint>

#define BATCH 1024
#define L 32
#define D 128
#define NNODE 50000
#define ROWS (BATCH * L)           // 32768
#define RD   (ROWS * D)            // 4194304
#define BD   (BATCH * D)           // 131072
#define ED   (NNODE * D)           // 6400000

// ---------------- float scratch (final only) ----------------
#define F_FIN  0L
__device__ float g_f[RD];
__device__ float g_bio[640];        // concat(b_in, b_out, zeros[384])

// ---------------- fp16 planes ----------------
#define H_GA   0L                   // gathered emb [ROWS,128]
#define H_A    ((long)RD)           // concat a [ROWS,256]
#define H_IT   (3L * RD)            // intra [ROWS,128]
#define H_FN   (4L * RD)            // final fp16 [ROWS,128]
#define H_IE   (5L * RD)            // inter [ROWS,128]
#define H_HG   (6L * RD)            // [ROWS,640] hin|hout|gh; later [ROWS,384] gh2
#define H_GI   (11L * RD)           // [ROWS,384]
#define H_FW2  (14L * RD)           // [ROWS,128]
#define H_HS   (15L * RD)           // [1024,128]
#define H_EB   (15L * RD + BD)      // emb [50000,128]
#define HW_WIOU (15L * RD + BD + (long)ED)  // [640,128]
#define HW_WA   (HW_WIOU + 81920L)          // [384,256]
#define HW_WI   (HW_WA + 98304L)            // [384,128]
#define HW_WH   (HW_WI + 49152L)
#define HW_W2   (HW_WH + 49152L)            // [128,128]
#define H_TOTAL (HW_W2 + 16384L)
__device__ __half g_h[H_TOTAL];

// ---------------- helpers ----------------
__device__ __forceinline__ uint32_t smem_u32(const void* p) {
    uint32_t a;
    asm("{ .reg .u64 t; cvta.to.shared.u64 t, %1; cvt.u32.u64 %0, t; }" : "=r"(a) : "l"(p));
    return a;
}
__device__ __forceinline__ float sigf(float x) { return 1.0f / (1.0f + expf(-x)); }

__device__ __forceinline__ void mma_f16(float* d, const uint32_t* a, const uint32_t* b) {
    asm volatile(
        "mma.sync.aligned.m16n8k16.row.col.f32.f16.f16.f32 "
        "{%0,%1,%2,%3}, {%4,%5,%6,%7}, {%8,%9}, {%0,%1,%2,%3};"
        : "+f"(d[0]), "+f"(d[1]), "+f"(d[2]), "+f"(d[3])
        : "r"(a[0]), "r"(a[1]), "r"(a[2]), "r"(a[3]), "r"(b[0]), "r"(b[1]));
}
__device__ __forceinline__ void ldsm4(uint32_t* r, uint32_t a) {
    asm volatile("ldmatrix.sync.aligned.m8n8.x4.shared.b16 {%0,%1,%2,%3}, [%4];"
        : "=r"(r[0]), "=r"(r[1]), "=r"(r[2]), "=r"(r[3]) : "r"(a));
}

// ================= single-pass fp16 GEMM, 128x128 tile, 3-stage pipeline =========
// C[M,N] = A[M,K] @ B[N,K]^T (+bias). fp32 accum.
// Block 128x128, 8 warps (2m x 4n), warp tile 64x32, K-chunk 32, 2 CTAs/SM.
// 3 smem stages, wait_group 1 -> prefetch has 2 compute phases to land.
// Output: fp16 to g_h+ch_off (Cf==null) or fp32 to Cf (scores).
#define APLB (128 * 80)
#define BPLB (128 * 80)
#define STAGEB (APLB + BPLB)        // 20480
#define GEMM_SMEM (3 * STAGEB)      // 61440 (needs MaxDynamicSharedMemorySize opt-in!)

__global__ void __launch_bounds__(256, 2) gemm_f16(
    long a_off, long b_off,
    const float* __restrict__ bias_ext, int bias_mode,
    float* __restrict__ Cf, long ch_off, int N, int K)
{
    extern __shared__ __align__(16) char dsm[];
    const __half* A = g_h + a_off;
    const __half* B = g_h + b_off;
    const float* bias = (bias_mode == 1) ? bias_ext : (bias_mode == 2 ? g_bio : nullptr);

    const int tid = threadIdx.x;
    const int warp = tid >> 5, lane = tid & 31;
    const int wm = warp & 1, wn = warp >> 1;          // 2m x 4n
    const int g = lane >> 2, tig = lane & 3;

    const long bm = (long)blockIdx.x * 128;
    const int bn = blockIdx.y * 128;
    const int nsize = min(128, N - bn);

    const int fr = tid >> 1;
    const int fc = (tid & 1) * 16;
    const long arow = bm + fr;
    const long brow = bn + (fr < nsize ? fr : 0);
    const int bok = (fr < nsize) ? 16 : 0;
    const uint32_t smb = smem_u32(dsm);
    const uint32_t doff = (uint32_t)(fr * 80 + fc * 2);

    const uint32_t laneA = (uint32_t)(((lane & 7) + (((lane >> 3) & 1) << 3)) * 80 + (lane >> 4) * 16);
    const uint32_t laneB = (uint32_t)(((lane & 7) + ((lane >> 4) << 3)) * 80 + ((lane >> 3) & 1) * 16);
    const uint32_t aBaseA = (uint32_t)(wm * 64 * 80) + laneA;
    const uint32_t aBaseB = (uint32_t)(wn * 32 * 80) + laneB;

    float acc[4][4][4];
#pragma unroll
    for (int i = 0; i < 4; i++)
#pragma unroll
        for (int j = 0; j < 4; j++)
#pragma unroll
            for (int v = 0; v < 4; v++) acc[i][j][v] = 0.f;

#define LOADF(c_, st_) do {                                                            \
    const long k0_ = (long)(c_) * 32;                                                  \
    const uint32_t b_ = smb + (uint32_t)(st_) * STAGEB;                                \
    const __half* pa_ = A + arow * K + k0_ + fc;                                       \
    const __half* pb_ = B + brow * K + k0_ + fc;                                       \
    asm volatile("cp.async.cg.shared.global [%0], [%1], 16;" :: "r"(b_ + doff), "l"(pa_)); \
    asm volatile("cp.async.cg.shared.global [%0], [%1], 16;" :: "r"(b_ + doff + 16), "l"(pa_ + 8)); \
    asm volatile("cp.async.cg.shared.global [%0], [%1], 16, %2;" :: "r"(b_ + APLB + doff), "l"(pb_), "r"(bok)); \
    asm volatile("cp.async.cg.shared.global [%0], [%1], 16, %2;" :: "r"(b_ + APLB + doff + 16), "l"(pb_ + 8), "r"(bok)); \
    asm volatile("cp.async.commit_group;");                                            \
} while (0)

    const int nch = K / 32;
    LOADF(0, 0);
    if (nch > 1) LOADF(1, 1);
    int st = 0, stp2 = (nch > 1) ? 2 : 1;   // stage of chunk c, and of chunk c+2
    for (int c = 0; c < nch; c++) {
        if (c + 1 < nch) {
            asm volatile("cp.async.wait_group 1;");
        } else {
            asm volatile("cp.async.wait_group 0;");
        }
        __syncthreads();
        if (c + 2 < nch) LOADF(c + 2, stp2);

        const uint32_t stb = smb + (uint32_t)st * STAGEB;
        const uint32_t pA = stb + aBaseA;
        const uint32_t pB = stb + APLB + aBaseB;

#pragma unroll
        for (int ks = 0; ks < 2; ks++) {
            const uint32_t ko = (uint32_t)(ks * 32);
            uint32_t af[4][4], bf[4][2];
#pragma unroll
            for (int mf = 0; mf < 4; mf++)
                ldsm4(af[mf], pA + (uint32_t)(mf * 16 * 80) + ko);
#pragma unroll
            for (int np = 0; np < 2; np++) {
                uint32_t bt[4];
                ldsm4(bt, pB + (uint32_t)(np * 16 * 80) + ko);
                bf[np * 2][0] = bt[0]; bf[np * 2][1] = bt[1];
                bf[np * 2 + 1][0] = bt[2]; bf[np * 2 + 1][1] = bt[3];
            }
#pragma unroll
            for (int mf = 0; mf < 4; mf++)
#pragma unroll
                for (int nf = 0; nf < 4; nf++)
                    mma_f16(acc[mf][nf], af[mf], bf[nf]);
        }
        st = (st + 1 == 3) ? 0 : st + 1;
        stp2 = (stp2 + 1 == 3) ? 0 : stp2 + 1;
    }

    __half* Ch = g_h + ch_off;
#pragma unroll
    for (int mf = 0; mf < 4; mf++) {
        const long row = bm + wm * 64 + mf * 16 + g;
#pragma unroll
        for (int nf = 0; nf < 4; nf++) {
            const int col = bn + wn * 32 + nf * 8 + tig * 2;
            if (col < N) {
                float bx = bias ? bias[col] : 0.f;
                float by = bias ? bias[col + 1] : 0.f;
                float v0 = acc[mf][nf][0] + bx, v1 = acc[mf][nf][1] + by;
                float v2 = acc[mf][nf][2] + bx, v3 = acc[mf][nf][3] + by;
                if (Cf) {
                    *(float2*)&Cf[row * N + col]       = make_float2(v0, v1);
                    *(float2*)&Cf[(row + 8) * N + col] = make_float2(v2, v3);
                } else {
                    *(__half2*)&Ch[row * N + col]       = __floats2half2_rn(v0, v1);
                    *(__half2*)&Ch[(row + 8) * N + col] = __floats2half2_rn(v2, v3);
                }
            }
        }
    }
#undef LOADF
}

// ================= fused prep =================
#define PREP_TOTAL (32768L + 49152 + 640 + 98304 + 49152 + 49152 + 16384 + (long)ED + 2L * RD)
__global__ void __launch_bounds__(256) prep_all(
    const float* __restrict__ W_in, const float* __restrict__ b_in,
    const float* __restrict__ W_out, const float* __restrict__ b_out,
    const float* __restrict__ W_a, const float* __restrict__ U_h,
    const float* __restrict__ Wi, const float* __restrict__ Wh,
    const float* __restrict__ W2,
    const float* __restrict__ emb, const float* __restrict__ inter,
    const int* __restrict__ items)
{
    long i = (long)blockIdx.x * 256 + threadIdx.x;
    if (i < 32768) {                                    // Wio rows 0..255 of [640,128]
        int n = (int)(i >> 7), k = (int)(i & 127);
        float v = (n < 128) ? W_in[k * 128 + n] : W_out[k * 128 + (n - 128)];
        g_h[HW_WIOU + i] = __float2half(v);
        return;
    }
    i -= 32768;
    if (i < 49152) {                                    // U_h rows 256..639
        int n = (int)(i >> 7), k = (int)(i & 127);
        g_h[HW_WIOU + 32768 + i] = __float2half(U_h[(long)k * 384 + n]);
        return;
    }
    i -= 49152;
    if (i < 640) {
        g_bio[i] = (i < 128) ? b_in[i] : (i < 256 ? b_out[i - 128] : 0.f);
        return;
    }
    i -= 640;
    if (i < 98304) {                                    // W_a [384,256]
        int n = (int)(i >> 8), k = (int)(i & 255);
        g_h[HW_WA + i] = __float2half(W_a[(long)k * 384 + n]);
        return;
    }
    i -= 98304;
    if (i < 49152) {                                    // Wi [384,128]
        int n = (int)(i >> 7), k = (int)(i & 127);
        g_h[HW_WI + i] = __float2half(Wi[(long)k * 384 + n]);
        return;
    }
    i -= 49152;
    if (i < 49152) {                                    // Wh [384,128]
        int n = (int)(i >> 7), k = (int)(i & 127);
        g_h[HW_WH + i] = __float2half(Wh[(long)k * 384 + n]);
        return;
    }
    i -= 49152;
    if (i < 16384) {                                    // W2 [128,128]
        int n = (int)(i >> 7), k = (int)(i & 127);
        g_h[HW_W2 + i] = __float2half(W2[(long)k * 128 + n]);
        return;
    }
    i -= 16384;
    if (i < (long)ED) {
        g_h[H_EB + i] = __float2half(emb[i]);
        return;
    }
    i -= (long)ED;
    if (i < (long)RD) {
        g_h[H_IE + i] = __float2half(inter[i]);
        return;
    }
    i -= (long)RD;
    if (i < (long)RD) {
        int row = (int)(i >> 7), d = (int)(i & 127);
        g_h[H_GA + i] = __float2half(emb[(long)items[row] * D + d]);
    }
}

// ================= adjacency (hio = cols 0..255 of fp16 [ROWS,640]) =============
__global__ void __launch_bounds__(128) adj_kernel(const float* __restrict__ Ain, const float* __restrict__ Aout) {
    const __half* hg = g_h + H_HG;
    const int b = blockIdx.x, d = threadIdx.x;
    __shared__ float sAi[L * L], sAo[L * L], shi[L * D], sho[L * D];
    const float* Aib = Ain + (long)b * L * L;
    const float* Aob = Aout + (long)b * L * L;
    for (int i = d; i < L * L; i += 128) { sAi[i] = Aib[i]; sAo[i] = Aob[i]; }
    for (int i = d; i < L * D; i += 128) {
        int m = i >> 7, dd = i & 127;
        long r = ((long)b * L + m) * 640;
        shi[i] = __half2float(hg[r + dd]);
        sho[i] = __half2float(hg[r + 128 + dd]);
    }
    __syncthreads();
    for (int l = 0; l < L; l++) {
        float si = 0.f, so = 0.f;
#pragma unroll 8
        for (int m = 0; m < L; m++) {
            si += sAi[l * L + m] * shi[m * D + d];
            so += sAo[l * L + m] * sho[m * D + d];
        }
        long o = ((long)b * L + l) * 256;
        g_h[H_A + o + d]       = __float2half(si);
        g_h[H_A + o + 128 + d] = __float2half(so);
    }
}

// ================= GRU kernels (fp16 gate inputs) =================
__global__ void __launch_bounds__(256) gru1_kernel(const int* __restrict__ items, const float* __restrict__ emb) {
    long i = (long)blockIdx.x * 256 + threadIdx.x;
    if (i >= (long)RD) return;
    int row = (int)(i >> 7), d = (int)(i & 127);
    const __half* gi = g_h + H_GI + (long)row * 384;
    const __half* gh = g_h + H_HG + (long)row * 640 + 256;
    float r = sigf(__half2float(gi[d]) + __half2float(gh[d]));
    float z = sigf(__half2float(gi[128 + d]) + __half2float(gh[128 + d]));
    float n = tanhf(__half2float(gi[256 + d]) + r * __half2float(gh[256 + d]));
    float hp = emb[(long)items[row] * D + d];
    g_h[H_IT + i] = __float2half((1.f - z) * n + z * hp);
}

__global__ void __launch_bounds__(256) gru2_kernel(const float* __restrict__ inter) {
    long i = (long)blockIdx.x * 256 + threadIdx.x;
    if (i >= (long)RD) return;
    int row = (int)(i >> 7), d = (int)(i & 127);
    const __half* gi = g_h + H_GI + (long)row * 384;
    const __half* gh = g_h + H_HG + (long)row * 384;
    float r = sigf(__half2float(gi[d]) + __half2float(gh[d]));
    float z = sigf(__half2float(gi[128 + d]) + __half2float(gh[128 + d]));
    float n = tanhf(__half2float(gi[256 + d]) + r * __half2float(gh[256 + d]));
    float v = (1.f - z) * n + z * inter[i];
    g_f[F_FIN + i] = v;
    g_h[H_FN + i] = __float2half(v);
}

// ================= attention readout =================
__global__ void __launch_bounds__(128) readout_kernel(
    const int* __restrict__ seq_len,
    const float* __restrict__ W1, const float* __restrict__ b1,
    const float* __restrict__ wq, const float* __restrict__ bq,
    const float* __restrict__ W3, const float* __restrict__ b3)
{
    const float* fin = g_f + F_FIN;
    const __half* fW2 = g_h + H_FW2;
    const int b = blockIdx.x, d = threadIdx.x;
    __shared__ float svn[D], sg_sh[D], gmat[L * D], alpha[L];

    const int sl = seq_len[b];
    const float* finb = fin + (long)b * L * D;
    svn[d] = finb[(long)(sl - 1) * D + d];
    __syncthreads();

    float q = b1[d];
    for (int k = 0; k < D; k++) q += svn[k] * W1[k * D + d];

    const __half* fW2b = fW2 + (long)b * L * D;
    for (int l = 0; l < L; l++)
        gmat[l * D + d] = sigf(q + __half2float(fW2b[l * D + d]));
    __syncthreads();

    int w = d >> 5, lane = d & 31;
    for (int l = w; l < L; l += 4) {
        float p = 0.f;
        for (int kk = lane; kk < D; kk += 32) p += gmat[l * D + kk] * wq[kk];
#pragma unroll
        for (int off = 16; off; off >>= 1) p += __shfl_xor_sync(0xFFFFFFFFu, p, off);
        if (lane == 0) alpha[l] = p + bq[0];
    }
    __syncthreads();

    float sg = 0.f;
    for (int l = 0; l < sl; l++) sg += alpha[l] * finb[(long)l * D + d];
    sg_sh[d] = sg;
    __syncthreads();

    float o = b3[d];
    for (int k = 0; k < D; k++) {
        o += svn[k]   * W3[k * D + d];
        o += sg_sh[k] * W3[(D + k) * D + d];
    }
    g_h[H_HS + (long)b * D + d] = __float2half(o);
}

// ================= launcher: pure kernel launches (+ one-time attr opt-in) =======
extern "C" void kernel_launch(void* const* d_in, const int* in_sizes, int n_in,
                              void* d_out, int out_size)
{
    const int*   items  = (const int*)d_in[0];
    const float* A_in   = (const float*)d_in[1];
    const float* A_out  = (const float*)d_in[2];
    const float* inter  = (const float*)d_in[3];
    const int*   seqlen = (const int*)d_in[4];
    const float* emb    = (const float*)d_in[5];
    const float* W_in   = (const float*)d_in[6];
    const float* b_in   = (const float*)d_in[7];
    const float* W_out  = (const float*)d_in[8];
    const float* b_out  = (const float*)d_in[9];
    const float* W_a    = (const float*)d_in[10];
    const float* U_h    = (const float*)d_in[11];
    const float* b_gru  = (const float*)d_in[12];
    const float* Wi     = (const float*)d_in[13];
    const float* bi     = (const float*)d_in[14];
    const float* Wh     = (const float*)d_in[15];
    const float* bh     = (const float*)d_in[16];
    const float* W1     = (const float*)d_in[17];
    const float* b1     = (const float*)d_in[18];
    const float* W2     = (const float*)d_in[19];
    const float* b2     = (const float*)d_in[20];
    const float* wq     = (const float*)d_in[21];
    const float* bq     = (const float*)d_in[22];
    const float* W3     = (const float*)d_in[23];
    const float* b3     = (const float*)d_in[24];
    float* scores = (float*)d_out;

    // 61440 B dynamic smem > 48KB default: opt-in required (this was the R15 failure).
    cudaFuncSetAttribute(gemm_f16, cudaFuncAttributeMaxDynamicSharedMemorySize, GEMM_SMEM);

    const int MT = ROWS / 128;   // 256 M-tiles

    prep_all<<<(int)((PREP_TOTAL + 255) / 256), 256>>>(W_in, b_in, W_out, b_out, W_a, U_h,
                                                       Wi, Wh, W2, emb, inter, items);
    // [hio | gh] = gathered @ [W_in|W_out|U_h] + [bio|0]   (N=640, K=128)
    gemm_f16<<<dim3(MT, 5), 256, GEMM_SMEM>>>(H_GA, HW_WIOU, nullptr, 2, nullptr, H_HG, 640, 128);
    adj_kernel<<<BATCH, 128>>>(A_in, A_out);
    gemm_f16<<<dim3(MT, 3), 256, GEMM_SMEM>>>(H_A, HW_WA, b_gru, 1, nullptr, H_GI, 384, 256);
    gru1_kernel<<<(RD + 255) / 256, 256>>>(items, emb);
    gemm_f16<<<dim3(MT, 3), 256, GEMM_SMEM>>>(H_IT, HW_WI, bi, 1, nullptr, H_GI, 384, 128);
    gemm_f16<<<dim3(MT, 3), 256, GEMM_SMEM>>>(H_IE, HW_WH, bh, 1, nullptr, H_HG, 384, 128);
    gru2_kernel<<<(RD + 255) / 256, 256>>>(inter);
    gemm_f16<<<dim3(MT, 1), 256, GEMM_SMEM>>>(H_FN, HW_W2, b2, 1, nullptr, H_FW2, 128, 128);
    readout_kernel<<<BATCH, 128>>>(seqlen, W1, b1, wq, bq, W3, b3);
    // scores = hs @ emb^T  (fp32 output to d_out)
    gemm_f16<<<dim3(BATCH / 128, (NNODE + 127) / 128), 256, GEMM_SMEM>>>(
        H_HS, H_EB, nullptr, 0, scores, 0, NNODE, 128);
}

// round 17
// speedup vs baseline: 1.4979x; 1.0228x over previous
#include <cuda_runtime.h>
#include <cuda_fp16.h>
#include <math.h>
#include <cstdint>

#define BATCH 1024
#define L 32
#define D 128
#define NNODE 50000
#define ROWS (BATCH * L)           // 32768
#define RD   (ROWS * D)            // 4194304
#define BD   (BATCH * D)           // 131072
#define ED   (NNODE * D)           // 6400000

// ---------------- float scratch (final only) ----------------
#define F_FIN  0L
__device__ float g_f[RD];
__device__ float g_bio[640];        // concat(b_in, b_out, zeros[384])

// ---------------- fp16 planes ----------------
#define H_GA   0L                   // gathered emb [ROWS,128]
#define H_A    ((long)RD)           // concat a [ROWS,256]
#define H_IT   (3L * RD)            // intra [ROWS,128]
#define H_FN   (4L * RD)            // final fp16 [ROWS,128]
#define H_IE   (5L * RD)            // inter [ROWS,128]
#define H_HG   (6L * RD)            // [ROWS,640] hin|hout|gh; later [ROWS,384] gh2
#define H_GI   (11L * RD)           // [ROWS,384]
#define H_FW2  (14L * RD)           // [ROWS,128]
#define H_HS   (15L * RD)           // [1024,128]
#define H_EB   (15L * RD + BD)      // emb [50000,128]
#define HW_WIOU (15L * RD + BD + (long)ED)  // [640,128]
#define HW_WA   (HW_WIOU + 81920L)          // [384,256]
#define HW_WI   (HW_WA + 98304L)            // [384,128]
#define HW_WH   (HW_WI + 49152L)
#define HW_W2   (HW_WH + 49152L)            // [128,128]
#define H_TOTAL (HW_W2 + 16384L)
__device__ __half g_h[H_TOTAL];

// ---------------- helpers ----------------
__device__ __forceinline__ uint32_t smem_u32(const void* p) {
    uint32_t a;
    asm("{ .reg .u64 t; cvta.to.shared.u64 t, %1; cvt.u32.u64 %0, t; }" : "=r"(a) : "l"(p));
    return a;
}
__device__ __forceinline__ float sigf(float x) { return 1.0f / (1.0f + expf(-x)); }

__device__ __forceinline__ void mma_f16(float* d, const uint32_t* a, const uint32_t* b) {
    asm volatile(
        "mma.sync.aligned.m16n8k16.row.col.f32.f16.f16.f32 "
        "{%0,%1,%2,%3}, {%4,%5,%6,%7}, {%8,%9}, {%0,%1,%2,%3};"
        : "+f"(d[0]), "+f"(d[1]), "+f"(d[2]), "+f"(d[3])
        : "r"(a[0]), "r"(a[1]), "r"(a[2]), "r"(a[3]), "r"(b[0]), "r"(b[1]));
}
__device__ __forceinline__ void ldsm4(uint32_t* r, uint32_t a) {
    asm volatile("ldmatrix.sync.aligned.m8n8.x4.shared.b16 {%0,%1,%2,%3}, [%4];"
        : "=r"(r[0]), "=r"(r[1]), "=r"(r[2]), "=r"(r[3]) : "r"(a));
}

// ================= single-pass fp16 GEMM, 128x128 tile, 3-stage pipeline =========
// blockIdx.z selects between parameter set 0 and set 1 (for merged launches).
#define APLB (128 * 80)
#define BPLB (128 * 80)
#define STAGEB (APLB + BPLB)        // 20480
#define GEMM_SMEM (3 * STAGEB)      // 61440 (needs opt-in)

__global__ void __launch_bounds__(256, 2) gemm_f16(
    long a_off, long b_off,
    const float* __restrict__ bias_ext, int bias_mode,
    float* __restrict__ Cf, long ch_off, int N, int K,
    long a_off2, long b_off2, const float* __restrict__ bias2, long ch_off2)
{
    extern __shared__ __align__(16) char dsm[];
    if (blockIdx.z == 1) { a_off = a_off2; b_off = b_off2; bias_ext = bias2; ch_off = ch_off2; }
    const __half* A = g_h + a_off;
    const __half* B = g_h + b_off;
    const float* bias = (bias_mode == 1) ? bias_ext : (bias_mode == 2 ? g_bio : nullptr);

    const int tid = threadIdx.x;
    const int warp = tid >> 5, lane = tid & 31;
    const int wm = warp & 1, wn = warp >> 1;          // 2m x 4n
    const int g = lane >> 2, tig = lane & 3;

    const long bm = (long)blockIdx.x * 128;
    const int bn = blockIdx.y * 128;
    const int nsize = min(128, N - bn);

    const int fr = tid >> 1;
    const int fc = (tid & 1) * 16;
    const long arow = bm + fr;
    const long brow = bn + (fr < nsize ? fr : 0);
    const int bok = (fr < nsize) ? 16 : 0;
    const uint32_t smb = smem_u32(dsm);
    const uint32_t doff = (uint32_t)(fr * 80 + fc * 2);

    const uint32_t laneA = (uint32_t)(((lane & 7) + (((lane >> 3) & 1) << 3)) * 80 + (lane >> 4) * 16);
    const uint32_t laneB = (uint32_t)(((lane & 7) + ((lane >> 4) << 3)) * 80 + ((lane >> 3) & 1) * 16);
    const uint32_t aBaseA = (uint32_t)(wm * 64 * 80) + laneA;
    const uint32_t aBaseB = (uint32_t)(wn * 32 * 80) + laneB;

    float acc[4][4][4];
#pragma unroll
    for (int i = 0; i < 4; i++)
#pragma unroll
        for (int j = 0; j < 4; j++)
#pragma unroll
            for (int v = 0; v < 4; v++) acc[i][j][v] = 0.f;

#define LOADF(c_, st_) do {                                                            \
    const long k0_ = (long)(c_) * 32;                                                  \
    const uint32_t b_ = smb + (uint32_t)(st_) * STAGEB;                                \
    const __half* pa_ = A + arow * K + k0_ + fc;                                       \
    const __half* pb_ = B + brow * K + k0_ + fc;                                       \
    asm volatile("cp.async.cg.shared.global [%0], [%1], 16;" :: "r"(b_ + doff), "l"(pa_)); \
    asm volatile("cp.async.cg.shared.global [%0], [%1], 16;" :: "r"(b_ + doff + 16), "l"(pa_ + 8)); \
    asm volatile("cp.async.cg.shared.global [%0], [%1], 16, %2;" :: "r"(b_ + APLB + doff), "l"(pb_), "r"(bok)); \
    asm volatile("cp.async.cg.shared.global [%0], [%1], 16, %2;" :: "r"(b_ + APLB + doff + 16), "l"(pb_ + 8), "r"(bok)); \
    asm volatile("cp.async.commit_group;");                                            \
} while (0)

    const int nch = K / 32;
    LOADF(0, 0);
    if (nch > 1) LOADF(1, 1);
    int st = 0, stp2 = (nch > 1) ? 2 : 1;
    for (int c = 0; c < nch; c++) {
        if (c + 1 < nch) {
            asm volatile("cp.async.wait_group 1;");
        } else {
            asm volatile("cp.async.wait_group 0;");
        }
        __syncthreads();
        if (c + 2 < nch) LOADF(c + 2, stp2);

        const uint32_t stb = smb + (uint32_t)st * STAGEB;
        const uint32_t pA = stb + aBaseA;
        const uint32_t pB = stb + APLB + aBaseB;

#pragma unroll
        for (int ks = 0; ks < 2; ks++) {
            const uint32_t ko = (uint32_t)(ks * 32);
            uint32_t af[4][4], bf[4][2];
#pragma unroll
            for (int mf = 0; mf < 4; mf++)
                ldsm4(af[mf], pA + (uint32_t)(mf * 16 * 80) + ko);
#pragma unroll
            for (int np = 0; np < 2; np++) {
                uint32_t bt[4];
                ldsm4(bt, pB + (uint32_t)(np * 16 * 80) + ko);
                bf[np * 2][0] = bt[0]; bf[np * 2][1] = bt[1];
                bf[np * 2 + 1][0] = bt[2]; bf[np * 2 + 1][1] = bt[3];
            }
#pragma unroll
            for (int mf = 0; mf < 4; mf++)
#pragma unroll
                for (int nf = 0; nf < 4; nf++)
                    mma_f16(acc[mf][nf], af[mf], bf[nf]);
        }
        st = (st + 1 == 3) ? 0 : st + 1;
        stp2 = (stp2 + 1 == 3) ? 0 : stp2 + 1;
    }

    __half* Ch = g_h + ch_off;
#pragma unroll
    for (int mf = 0; mf < 4; mf++) {
        const long row = bm + wm * 64 + mf * 16 + g;
#pragma unroll
        for (int nf = 0; nf < 4; nf++) {
            const int col = bn + wn * 32 + nf * 8 + tig * 2;
            if (col < N) {
                float bx = bias ? bias[col] : 0.f;
                float by = bias ? bias[col + 1] : 0.f;
                float v0 = acc[mf][nf][0] + bx, v1 = acc[mf][nf][1] + by;
                float v2 = acc[mf][nf][2] + bx, v3 = acc[mf][nf][3] + by;
                if (Cf) {
                    *(float2*)&Cf[row * N + col]       = make_float2(v0, v1);
                    *(float2*)&Cf[(row + 8) * N + col] = make_float2(v2, v3);
                } else {
                    *(__half2*)&Ch[row * N + col]       = __floats2half2_rn(v0, v1);
                    *(__half2*)&Ch[(row + 8) * N + col] = __floats2half2_rn(v2, v3);
                }
            }
        }
    }
#undef LOADF
}

// ================= scores GEMM: A persistent, 4 N-tiles per CTA =================
// C[1024, N] = A[1024,128] @ B[N,128]^T, fp32 out.
// A (128x128) loaded ONCE into smem (4 k-chunks); B streamed through 3-stage ring
// continuously across 16 global chunks (4 tiles x 4 k-chunks).
#define S_NT 4
#define SA_CH (128 * 80)
#define SB_ST (128 * 80)
#define S_SMEM (4 * SA_CH + 3 * SB_ST)   // 71680 (needs opt-in)

__global__ void __launch_bounds__(256, 2) gemm_scores(
    long a_off, long b_off, float* __restrict__ Cf, int N)
{
    extern __shared__ __align__(16) char dsm[];
    const __half* A = g_h + a_off;
    const __half* B = g_h + b_off;

    const int tid = threadIdx.x;
    const int warp = tid >> 5, lane = tid & 31;
    const int wm = warp & 1, wn = warp >> 1;
    const int g = lane >> 2, tig = lane & 3;

    const long bm = (long)blockIdx.x * 128;
    const int bn0 = blockIdx.y * (128 * S_NT);

    const int fr = tid >> 1;
    const int fc = (tid & 1) * 16;
    const uint32_t smb = smem_u32(dsm);
    const uint32_t doff = (uint32_t)(fr * 80 + fc * 2);

    const uint32_t laneA = (uint32_t)(((lane & 7) + (((lane >> 3) & 1) << 3)) * 80 + (lane >> 4) * 16);
    const uint32_t laneB = (uint32_t)(((lane & 7) + ((lane >> 4) << 3)) * 80 + ((lane >> 3) & 1) * 16);
    const uint32_t aBaseA = (uint32_t)(wm * 64 * 80) + laneA;
    const uint32_t aBaseB = (uint32_t)(wn * 32 * 80) + laneB;

    // A prolog: all 4 k-chunks, one commit group
    {
        const __half* pa = A + (bm + fr) * 128 + fc;
#pragma unroll
        for (int kc = 0; kc < 4; kc++) {
            const uint32_t dst = smb + (uint32_t)kc * SA_CH + doff;
            asm volatile("cp.async.cg.shared.global [%0], [%1], 16;" :: "r"(dst), "l"(pa + kc * 32));
            asm volatile("cp.async.cg.shared.global [%0], [%1], 16;" :: "r"(dst + 16), "l"(pa + kc * 32 + 8));
        }
        asm volatile("cp.async.commit_group;");
    }

#define LOADB(gc_) do {                                                                \
    const int t_ = (gc_) >> 2, c_ = (gc_) & 3;                                         \
    const int bn_ = bn0 + t_ * 128;                                                    \
    const int ok_ = (bn_ + fr < N) ? 16 : 0;                                           \
    const long brow_ = (long)bn_ + ((bn_ + fr < N) ? fr : 0);                          \
    const uint32_t dst_ = smb + 4 * SA_CH + (uint32_t)((gc_) % 3) * SB_ST + doff;      \
    const __half* pb_ = B + brow_ * 128 + c_ * 32 + fc;                                \
    asm volatile("cp.async.cg.shared.global [%0], [%1], 16, %2;" :: "r"(dst_), "l"(pb_), "r"(ok_)); \
    asm volatile("cp.async.cg.shared.global [%0], [%1], 16, %2;" :: "r"(dst_ + 16), "l"(pb_ + 8), "r"(ok_)); \
    asm volatile("cp.async.commit_group;");                                            \
} while (0)

    LOADB(0);
    LOADB(1);

    float acc[4][4][4];
    for (int gc = 0; gc < 4 * S_NT; gc++) {
        if (gc + 1 < 4 * S_NT) {
            asm volatile("cp.async.wait_group 1;");
        } else {
            asm volatile("cp.async.wait_group 0;");
        }
        __syncthreads();
        if (gc + 2 < 4 * S_NT) LOADB(gc + 2);

        const int t = gc >> 2, c = gc & 3;
        if (c == 0) {
#pragma unroll
            for (int i = 0; i < 4; i++)
#pragma unroll
                for (int j = 0; j < 4; j++)
#pragma unroll
                    for (int v = 0; v < 4; v++) acc[i][j][v] = 0.f;
        }

        const uint32_t pA = smb + (uint32_t)c * SA_CH + aBaseA;
        const uint32_t pB = smb + 4 * SA_CH + (uint32_t)(gc % 3) * SB_ST + aBaseB;

#pragma unroll
        for (int ks = 0; ks < 2; ks++) {
            const uint32_t ko = (uint32_t)(ks * 32);
            uint32_t af[4][4], bf[4][2];
#pragma unroll
            for (int mf = 0; mf < 4; mf++)
                ldsm4(af[mf], pA + (uint32_t)(mf * 16 * 80) + ko);
#pragma unroll
            for (int np = 0; np < 2; np++) {
                uint32_t bt[4];
                ldsm4(bt, pB + (uint32_t)(np * 16 * 80) + ko);
                bf[np * 2][0] = bt[0]; bf[np * 2][1] = bt[1];
                bf[np * 2 + 1][0] = bt[2]; bf[np * 2 + 1][1] = bt[3];
            }
#pragma unroll
            for (int mf = 0; mf < 4; mf++)
#pragma unroll
                for (int nf = 0; nf < 4; nf++)
                    mma_f16(acc[mf][nf], af[mf], bf[nf]);
        }

        if (c == 3) {
            const int bn = bn0 + t * 128;
#pragma unroll
            for (int mf = 0; mf < 4; mf++) {
                const long row = bm + wm * 64 + mf * 16 + g;
#pragma unroll
                for (int nf = 0; nf < 4; nf++) {
                    const int col = bn + wn * 32 + nf * 8 + tig * 2;
                    if (col < N) {
                        *(float2*)&Cf[row * N + col] =
                            make_float2(acc[mf][nf][0], acc[mf][nf][1]);
                        *(float2*)&Cf[(row + 8) * N + col] =
                            make_float2(acc[mf][nf][2], acc[mf][nf][3]);
                    }
                }
            }
        }
    }
#undef LOADB
}

// ================= fused prep =================
#define PREP_TOTAL (32768L + 49152 + 640 + 98304 + 49152 + 49152 + 16384 + (long)ED + 2L * RD)
__global__ void __launch_bounds__(256) prep_all(
    const float* __restrict__ W_in, const float* __restrict__ b_in,
    const float* __restrict__ W_out, const float* __restrict__ b_out,
    const float* __restrict__ W_a, const float* __restrict__ U_h,
    const float* __restrict__ Wi, const float* __restrict__ Wh,
    const float* __restrict__ W2,
    const float* __restrict__ emb, const float* __restrict__ inter,
    const int* __restrict__ items)
{
    long i = (long)blockIdx.x * 256 + threadIdx.x;
    if (i < 32768) {
        int n = (int)(i >> 7), k = (int)(i & 127);
        float v = (n < 128) ? W_in[k * 128 + n] : W_out[k * 128 + (n - 128)];
        g_h[HW_WIOU + i] = __float2half(v);
        return;
    }
    i -= 32768;
    if (i < 49152) {
        int n = (int)(i >> 7), k = (int)(i & 127);
        g_h[HW_WIOU + 32768 + i] = __float2half(U_h[(long)k * 384 + n]);
        return;
    }
    i -= 49152;
    if (i < 640) {
        g_bio[i] = (i < 128) ? b_in[i] : (i < 256 ? b_out[i - 128] : 0.f);
        return;
    }
    i -= 640;
    if (i < 98304) {
        int n = (int)(i >> 8), k = (int)(i & 255);
        g_h[HW_WA + i] = __float2half(W_a[(long)k * 384 + n]);
        return;
    }
    i -= 98304;
    if (i < 49152) {
        int n = (int)(i >> 7), k = (int)(i & 127);
        g_h[HW_WI + i] = __float2half(Wi[(long)k * 384 + n]);
        return;
    }
    i -= 49152;
    if (i < 49152) {
        int n = (int)(i >> 7), k = (int)(i & 127);
        g_h[HW_WH + i] = __float2half(Wh[(long)k * 384 + n]);
        return;
    }
    i -= 49152;
    if (i < 16384) {
        int n = (int)(i >> 7), k = (int)(i & 127);
        g_h[HW_W2 + i] = __float2half(W2[(long)k * 128 + n]);
        return;
    }
    i -= 16384;
    if (i < (long)ED) {
        g_h[H_EB + i] = __float2half(emb[i]);
        return;
    }
    i -= (long)ED;
    if (i < (long)RD) {
        g_h[H_IE + i] = __float2half(inter[i]);
        return;
    }
    i -= (long)RD;
    if (i < (long)RD) {
        int row = (int)(i >> 7), d = (int)(i & 127);
        g_h[H_GA + i] = __float2half(emb[(long)items[row] * D + d]);
    }
}

// ================= adjacency =================
__global__ void __launch_bounds__(128) adj_kernel(const float* __restrict__ Ain, const float* __restrict__ Aout) {
    const __half* hg = g_h + H_HG;
    const int b = blockIdx.x, d = threadIdx.x;
    __shared__ float sAi[L * L], sAo[L * L], shi[L * D], sho[L * D];
    const float* Aib = Ain + (long)b * L * L;
    const float* Aob = Aout + (long)b * L * L;
    for (int i = d; i < L * L; i += 128) { sAi[i] = Aib[i]; sAo[i] = Aob[i]; }
    for (int i = d; i < L * D; i += 128) {
        int m = i >> 7, dd = i & 127;
        long r = ((long)b * L + m) * 640;
        shi[i] = __half2float(hg[r + dd]);
        sho[i] = __half2float(hg[r + 128 + dd]);
    }
    __syncthreads();
    for (int l = 0; l < L; l++) {
        float si = 0.f, so = 0.f;
#pragma unroll 8
        for (int m = 0; m < L; m++) {
            si += sAi[l * L + m] * shi[m * D + d];
            so += sAo[l * L + m] * sho[m * D + d];
        }
        long o = ((long)b * L + l) * 256;
        g_h[H_A + o + d]       = __float2half(si);
        g_h[H_A + o + 128 + d] = __float2half(so);
    }
}

// ================= GRU kernels =================
__global__ void __launch_bounds__(256) gru1_kernel(const int* __restrict__ items, const float* __restrict__ emb) {
    long i = (long)blockIdx.x * 256 + threadIdx.x;
    if (i >= (long)RD) return;
    int row = (int)(i >> 7), d = (int)(i & 127);
    const __half* gi = g_h + H_GI + (long)row * 384;
    const __half* gh = g_h + H_HG + (long)row * 640 + 256;
    float r = sigf(__half2float(gi[d]) + __half2float(gh[d]));
    float z = sigf(__half2float(gi[128 + d]) + __half2float(gh[128 + d]));
    float n = tanhf(__half2float(gi[256 + d]) + r * __half2float(gh[256 + d]));
    float hp = emb[(long)items[row] * D + d];
    g_h[H_IT + i] = __float2half((1.f - z) * n + z * hp);
}

__global__ void __launch_bounds__(256) gru2_kernel(const float* __restrict__ inter) {
    long i = (long)blockIdx.x * 256 + threadIdx.x;
    if (i >= (long)RD) return;
    int row = (int)(i >> 7), d = (int)(i & 127);
    const __half* gi = g_h + H_GI + (long)row * 384;
    const __half* gh = g_h + H_HG + (long)row * 384;
    float r = sigf(__half2float(gi[d]) + __half2float(gh[d]));
    float z = sigf(__half2float(gi[128 + d]) + __half2float(gh[128 + d]));
    float n = tanhf(__half2float(gi[256 + d]) + r * __half2float(gh[256 + d]));
    float v = (1.f - z) * n + z * inter[i];
    g_f[F_FIN + i] = v;
    g_h[H_FN + i] = __float2half(v);
}

// ================= attention readout =================
__global__ void __launch_bounds__(128) readout_kernel(
    const int* __restrict__ seq_len,
    const float* __restrict__ W1, const float* __restrict__ b1,
    const float* __restrict__ wq, const float* __restrict__ bq,
    const float* __restrict__ W3, const float* __restrict__ b3)
{
    const float* fin = g_f + F_FIN;
    const __half* fW2 = g_h + H_FW2;
    const int b = blockIdx.x, d = threadIdx.x;
    __shared__ float svn[D], sg_sh[D], gmat[L * D], alpha[L];

    const int sl = seq_len[b];
    const float* finb = fin + (long)b * L * D;
    svn[d] = finb[(long)(sl - 1) * D + d];
    __syncthreads();

    float q = b1[d];
    for (int k = 0; k < D; k++) q += svn[k] * W1[k * D + d];

    const __half* fW2b = fW2 + (long)b * L * D;
    for (int l = 0; l < L; l++)
        gmat[l * D + d] = sigf(q + __half2float(fW2b[l * D + d]));
    __syncthreads();

    int w = d >> 5, lane = d & 31;
    for (int l = w; l < L; l += 4) {
        float p = 0.f;
        for (int kk = lane; kk < D; kk += 32) p += gmat[l * D + kk] * wq[kk];
#pragma unroll
        for (int off = 16; off; off >>= 1) p += __shfl_xor_sync(0xFFFFFFFFu, p, off);
        if (lane == 0) alpha[l] = p + bq[0];
    }
    __syncthreads();

    float sg = 0.f;
    for (int l = 0; l < sl; l++) sg += alpha[l] * finb[(long)l * D + d];
    sg_sh[d] = sg;
    __syncthreads();

    float o = b3[d];
    for (int k = 0; k < D; k++) {
        o += svn[k]   * W3[k * D + d];
        o += sg_sh[k] * W3[(D + k) * D + d];
    }
    g_h[H_HS + (long)b * D + d] = __float2half(o);
}

// ================= launcher =================
extern "C" void kernel_launch(void* const* d_in, const int* in_sizes, int n_in,
                              void* d_out, int out_size)
{
    const int*   items  = (const int*)d_in[0];
    const float* A_in   = (const float*)d_in[1];
    const float* A_out  = (const float*)d_in[2];
    const float* inter  = (const float*)d_in[3];
    const int*   seqlen = (const int*)d_in[4];
    const float* emb    = (const float*)d_in[5];
    const float* W_in   = (const float*)d_in[6];
    const float* b_in   = (const float*)d_in[7];
    const float* W_out  = (const float*)d_in[8];
    const float* b_out  = (const float*)d_in[9];
    const float* W_a    = (const float*)d_in[10];
    const float* U_h    = (const float*)d_in[11];
    const float* b_gru  = (const float*)d_in[12];
    const float* Wi     = (const float*)d_in[13];
    const float* bi     = (const float*)d_in[14];
    const float* Wh     = (const float*)d_in[15];
    const float* bh     = (const float*)d_in[16];
    const float* W1     = (const float*)d_in[17];
    const float* b1     = (const float*)d_in[18];
    const float* W2     = (const float*)d_in[19];
    const float* b2     = (const float*)d_in[20];
    const float* wq     = (const float*)d_in[21];
    const float* bq     = (const float*)d_in[22];
    const float* W3     = (const float*)d_in[23];
    const float* b3     = (const float*)d_in[24];
    float* scores = (float*)d_out;

    cudaFuncSetAttribute(gemm_f16, cudaFuncAttributeMaxDynamicSharedMemorySize, GEMM_SMEM);
    cudaFuncSetAttribute(gemm_scores, cudaFuncAttributeMaxDynamicSharedMemorySize, S_SMEM);

    const int MT = ROWS / 128;   // 256 M-tiles

    prep_all<<<(int)((PREP_TOTAL + 255) / 256), 256>>>(W_in, b_in, W_out, b_out, W_a, U_h,
                                                       Wi, Wh, W2, emb, inter, items);
    // [hio | gh] = gathered @ [W_in|W_out|U_h] + [bio|0]   (N=640, K=128)
    gemm_f16<<<dim3(MT, 5, 1), 256, GEMM_SMEM>>>(H_GA, HW_WIOU, nullptr, 2, nullptr, H_HG, 640, 128,
                                                 0, 0, nullptr, 0);
    adj_kernel<<<BATCH, 128>>>(A_in, A_out);
    gemm_f16<<<dim3(MT, 3, 1), 256, GEMM_SMEM>>>(H_A, HW_WA, b_gru, 1, nullptr, H_GI, 384, 256,
                                                 0, 0, nullptr, 0);
    gru1_kernel<<<(RD + 255) / 256, 256>>>(items, emb);
    // merged: z=0 -> gi = intra@Wi+bi ; z=1 -> gh2 = inter@Wh+bh
    gemm_f16<<<dim3(MT, 3, 2), 256, GEMM_SMEM>>>(H_IT, HW_WI, bi, 1, nullptr, H_GI, 384, 128,
                                                 H_IE, HW_WH, bh, H_HG);
    gru2_kernel<<<(RD + 255) / 256, 256>>>(inter);
    gemm_f16<<<dim3(MT, 1, 1), 256, GEMM_SMEM>>>(H_FN, HW_W2, b2, 1, nullptr, H_FW2, 128, 128,
                                                 0, 0, nullptr, 0);
    readout_kernel<<<BATCH, 128>>>(seqlen, W1, b1, wq, bq, W3, b3);
    // scores = hs @ emb^T : A persistent, 4 N-tiles per CTA
    gemm_scores<<<dim3(BATCH / 128, (NNODE + 511) / 512), 256, S_SMEM>>>(
        H_HS, H_EB, scores, NNODE);
}